// round 3
// baseline (speedup 1.0000x reference)
#include <cuda_runtime.h>
#include <cstdint>

#define B_ 8
#define T_ 4096
#define D_ 256
#define H_ 256
#define G_ 768              // 3H
#define M_ (B_ * T_)        // 32768

// Scratch (static device allocations only)
__device__ float g_xg[(size_t)2 * B_ * T_ * G_];       // [dir][b][t][768]
__device__ float g_outc[(size_t)B_ * T_ * 2 * H_];     // [b][t][512]  (fwd | bwd)

// ---- scan dynamic smem layout (bytes) ----
#define SM_W      0                       // 96 cols x 256 K floats = 98304 B
#define SM_H      98304                   // 3 x 256 floats (triple-buffered h) = 3072 B
#define SM_MBAR   101376                  // 3 x 8 B mbarriers
#define SM_SCAN_BYTES 101504

// ---------------------------------------------------------------------------
// Kernel A: xg[d] = X @ Wi_d + bi_d    X:[32768,256] (row=b*T+t), Wi:[256,768]
// ---------------------------------------------------------------------------
__global__ void __launch_bounds__(256) k_xgemm(
    const float* __restrict__ X,
    const float* __restrict__ Wi_f, const float* __restrict__ bi_f,
    const float* __restrict__ Wi_b, const float* __restrict__ bi_b)
{
    const int d = blockIdx.z;
    const float* W  = d ? Wi_b : Wi_f;
    const float* bi = d ? bi_b : bi_f;
    float* out = g_xg + (size_t)d * M_ * G_;

    const int m0 = blockIdx.y * 64;
    const int n0 = blockIdx.x * 64;

    __shared__ float As[16][65];
    __shared__ float Bs[16][64];

    const int tid = threadIdx.x;
    const int ti = tid >> 4;
    const int tj = tid & 15;

    float acc[4][4];
#pragma unroll
    for (int i = 0; i < 4; ++i)
#pragma unroll
        for (int j = 0; j < 4; ++j) acc[i][j] = 0.f;

    for (int k0 = 0; k0 < D_; k0 += 16) {
#pragma unroll
        for (int p = 0; p < 4; ++p) {
            int idx = tid + p * 256;
            int r = idx >> 4, c = idx & 15;
            As[c][r] = X[(size_t)(m0 + r) * D_ + k0 + c];
        }
#pragma unroll
        for (int p = 0; p < 4; ++p) {
            int idx = tid + p * 256;
            int r = idx >> 6, c = idx & 63;
            Bs[r][c] = W[(size_t)(k0 + r) * G_ + n0 + c];
        }
        __syncthreads();
#pragma unroll
        for (int kk = 0; kk < 16; ++kk) {
            float av[4];
#pragma unroll
            for (int i = 0; i < 4; ++i) av[i] = As[kk][ti * 4 + i];
            float4 bq = *(const float4*)&Bs[kk][tj * 4];
            float bv4[4] = {bq.x, bq.y, bq.z, bq.w};
#pragma unroll
            for (int i = 0; i < 4; ++i)
#pragma unroll
                for (int j = 0; j < 4; ++j)
                    acc[i][j] = fmaf(av[i], bv4[j], acc[i][j]);
        }
        __syncthreads();
    }

#pragma unroll
    for (int j = 0; j < 4; ++j) {
        float bb = bi[n0 + tj * 4 + j];
#pragma unroll
        for (int i = 0; i < 4; ++i)
            out[(size_t)(m0 + ti * 4 + i) * G_ + n0 + tj * 4 + j] = acc[i][j] + bb;
    }
}

// ---------------------------------------------------------------------------
// Kernel B: clustered bidirectional GRU scan.
// 128 CTAs = 16 clusters of 8. Cluster = (dir, batch). CTA rank = hidden group
// (32 units, 96 gate columns, Wh slice 96KB in smem).
// Per step: 96 dots (lane = K-chunk, butterfly reduce), GRU elementwise,
// DSMEM push of 32 h values to all 8 peers, mbarrier arrive/wait. No L2 sync.
// ---------------------------------------------------------------------------
__global__ void __launch_bounds__(256, 1) __cluster_dims__(8, 1, 1)
k_scan(const float* __restrict__ Wh_f, const float* __restrict__ bhn_f,
       const float* __restrict__ Wh_b, const float* __restrict__ bhn_b)
{
    extern __shared__ char smem[];
    float* Wsm  = (float*)(smem + SM_W);
    float* hbuf = (float*)(smem + SM_H);     // hbuf[3][256]

    uint32_t smem_u32;
    asm("{ .reg .u64 t; cvta.to.shared.u64 t, %1; cvt.u32.u64 %0, t; }"
        : "=r"(smem_u32) : "l"(smem));
    const uint32_t hbuf_a = smem_u32 + SM_H;
    const uint32_t mbar_a = smem_u32 + SM_MBAR;

    const int bx   = blockIdx.x;
    const int rank = bx & 7;                 // hidden group (== cluster_ctarank)
    const int cid  = bx >> 3;
    const int d    = cid >> 3;               // direction
    const int b    = cid & 7;                // batch

    const float* Wh  = d ? Wh_b  : Wh_f;
    const float* bhn = d ? bhn_b : bhn_f;

    const int tid  = threadIdx.x;
    const int w    = tid >> 5;               // warp -> 4 units (12 cols)
    const int lane = tid & 31;

    // Load Wh slice: 96 cols (c = gate*32 + u_local) x 256 K. Coalesced over cols.
    for (int i = tid; i < 96 * 256; i += 256) {
        int c = i % 96, k = i / 96;
        int colg = (c >> 5) * H_ + rank * 32 + (c & 31);
        Wsm[c * 256 + k] = Wh[(size_t)k * G_ + colg];
    }
    // h0 = 0 in buffer 0
    hbuf[tid] = 0.f;
    if (tid == 0) {
#pragma unroll
        for (int i = 0; i < 3; ++i)
            asm volatile("mbarrier.init.shared.b64 [%0], %1;"
                         :: "r"(mbar_a + i * 8), "r"(8) : "memory");
    }
    __syncthreads();
    asm volatile("barrier.cluster.arrive.aligned;" ::: "memory");
    asm volatile("barrier.cluster.wait.aligned;"   ::: "memory");

    // initial arrive round on mbar[0] so the wait protocol is uniform
    if (w == 0 && lane < 8) {
        uint32_t rm;
        asm volatile("mapa.shared::cluster.u32 %0, %1, %2;"
                     : "=r"(rm) : "r"(mbar_a), "r"(lane));
        asm volatile("mbarrier.arrive.shared::cluster.b64 _, [%0];"
                     :: "r"(rm) : "memory");
    }

    const float bhn_u = (lane < 4) ? bhn[rank * 32 + w * 4 + lane] : 0.f;
    const float* xg_base = g_xg + ((size_t)(d * B_ + b)) * T_ * G_;

    // prefetch gi for step 0: lane cc<12 -> col gate=cc>>2, j=cc&3
    float giv = 0.f;
    {
        const int t0 = d ? (T_ - 1) : 0;
        if (lane < 12)
            giv = __ldg(xg_base + (size_t)t0 * G_ +
                        (lane >> 2) * H_ + rank * 32 + w * 4 + (lane & 3));
    }

    for (int s = 0; s < T_; ++s) {
        const int t  = d ? (T_ - 1 - s) : s;
        const int q3 = s / 3;
        const int p  = s - q3 * 3;                   // s % 3
        const unsigned par = (unsigned)(q3 & 1);

        // ---- wait for all 8 h-slices of step s (local smem mbarrier) ----
        {
            const uint32_t mb = mbar_a + p * 8;
            uint32_t done;
            asm volatile(
                "{\n\t.reg .pred pp;\n\t"
                "mbarrier.try_wait.parity.acquire.cta.shared::cta.b64 pp, [%1], %2;\n\t"
                "selp.b32 %0, 1, 0, pp;\n\t}"
                : "=r"(done) : "r"(mb), "r"(par) : "memory");
            if (!done) {
                asm volatile(
                    "{\n\t.reg .pred P1;\n\t"
                    "WL_%=:\n\t"
                    "mbarrier.try_wait.parity.acquire.cta.shared::cta.b64 P1, [%0], %1, 0x989680;\n\t"
                    "@P1 bra.uni WD_%=;\n\t"
                    "bra.uni WL_%=;\n\t"
                    "WD_%=:\n\t}"
                    :: "r"(mb), "r"(par) : "memory");
            }
            asm volatile("fence.acq_rel.cluster;" ::: "memory");  // see peers' DSMEM writes
        }

        // ---- h into registers: lane owns K chunk [lane*8, lane*8+8) ----
        const float* hp = hbuf + p * 256;
        float4 h0 = *(const float4*)(hp + lane * 8);
        float4 h1 = *(const float4*)(hp + lane * 8 + 4);

        // ---- 12 dot products (cols of this warp), butterfly-reduced ----
        float sums[12];
#pragma unroll
        for (int cc = 0; cc < 12; ++cc) {
            const int gate = cc >> 2, j = cc & 3;
            const float4* wr = (const float4*)(Wsm + (gate * 32 + w * 4 + j) * 256 + lane * 8);
            float4 w0 = wr[0], w1 = wr[1];
            float sa;
            sa = w0.x * h0.x;
            sa = fmaf(w0.y, h0.y, sa);
            sa = fmaf(w0.z, h0.z, sa);
            sa = fmaf(w0.w, h0.w, sa);
            sa = fmaf(w1.x, h1.x, sa);
            sa = fmaf(w1.y, h1.y, sa);
            sa = fmaf(w1.z, h1.z, sa);
            sa = fmaf(w1.w, h1.w, sa);
            sa += __shfl_xor_sync(0xFFFFFFFFu, sa, 16);
            sa += __shfl_xor_sync(0xFFFFFFFFu, sa, 8);
            sa += __shfl_xor_sync(0xFFFFFFFFu, sa, 4);
            sa += __shfl_xor_sync(0xFFFFFFFFu, sa, 2);
            sa += __shfl_xor_sync(0xFFFFFFFFu, sa, 1);
            sums[cc] = sa;
        }

        // ---- GRU elementwise (lanes 0..3 = this warp's 4 units) ----
        const int j = lane & 3;
        float gr = __shfl_sync(0xFFFFFFFFu, giv, j);
        float gz = __shfl_sync(0xFFFFFFFFu, giv, 4 + j);
        float gn = __shfl_sync(0xFFFFFFFFu, giv, 8 + j);
        float hn = 0.f;
        if (lane < 4) {
            float r = 1.f / (1.f + expf(-(gr + sums[j])));
            float z = 1.f / (1.f + expf(-(gz + sums[4 + j])));
            float n = tanhf(fmaf(r, sums[8 + j] + bhn_u, gn));
            float hprev = hp[rank * 32 + w * 4 + j];
            hn = fmaf(z, hprev - n, n);                 // (1-z)*n + z*h
            g_outc[((size_t)b * T_ + t) * (2 * H_) + d * H_ + rank * 32 + w * 4 + j] = hn;
        }

        if (s + 1 < T_) {
            const int pn = (p + 1 == 3) ? 0 : p + 1;

            // ---- push our 4 h values to all 8 peers (1 store per lane) ----
            float val = __shfl_sync(0xFFFFFFFFu, hn, j);
            uint32_t dst = hbuf_a + (uint32_t)pn * 1024 + (rank * 32 + w * 4 + j) * 4;
            uint32_t peer = lane >> 2;
            uint32_t rdst;
            asm volatile("mapa.shared::cluster.u32 %0, %1, %2;"
                         : "=r"(rdst) : "r"(dst), "r"(peer));
            asm volatile("st.shared::cluster.u32 [%0], %1;"
                         :: "r"(rdst), "r"(__float_as_uint(val)) : "memory");

            // prefetch gi for step s+1 (latency hidden behind sync)
            if (lane < 12) {
                const int tn = d ? (T_ - 2 - s) : (s + 1);
                giv = __ldg(xg_base + (size_t)tn * G_ +
                            (lane >> 2) * H_ + rank * 32 + w * 4 + (lane & 3));
            }

            __syncthreads();   // all warps' DSMEM stores issued

            if (w == 0 && lane < 8) {
                asm volatile("fence.acq_rel.cluster;" ::: "memory");
                uint32_t rm;
                asm volatile("mapa.shared::cluster.u32 %0, %1, %2;"
                             : "=r"(rm) : "r"(mbar_a + pn * 8), "r"(lane));
                asm volatile("mbarrier.arrive.shared::cluster.b64 _, [%0];"
                             :: "r"(rm) : "memory");
            }
        }
    }
}

// ---------------------------------------------------------------------------
// Kernel C: heads. out_combined [32768,512] @ (Wm|Wv) [512,256] + bias.
// J = exp(var head) -> d_out[0 : M*H);  h = mean head -> d_out[M*H : 2*M*H).
// ---------------------------------------------------------------------------
__global__ void __launch_bounds__(256) k_heads(
    const float* __restrict__ Wm, const float* __restrict__ bm,
    const float* __restrict__ Wv, const float* __restrict__ bv,
    float* __restrict__ out)
{
    const int n0 = blockIdx.x * 64;
    const int m0 = blockIdx.y * 64;
    const bool isV = (n0 >= 256);
    const float* W  = isV ? Wv : Wm;
    const float* bb = isV ? bv : bm;
    const int nw = n0 & 255;

    __shared__ float As[16][65];
    __shared__ float Bs[16][64];

    const int tid = threadIdx.x;
    const int ti = tid >> 4, tj = tid & 15;

    float acc[4][4];
#pragma unroll
    for (int i = 0; i < 4; ++i)
#pragma unroll
        for (int j = 0; j < 4; ++j) acc[i][j] = 0.f;

    for (int k0 = 0; k0 < 512; k0 += 16) {
#pragma unroll
        for (int p = 0; p < 4; ++p) {
            int idx = tid + p * 256;
            int r = idx >> 4, c = idx & 15;
            As[c][r] = g_outc[(size_t)(m0 + r) * 512 + k0 + c];
        }
#pragma unroll
        for (int p = 0; p < 4; ++p) {
            int idx = tid + p * 256;
            int r = idx >> 6, c = idx & 63;
            Bs[r][c] = W[(size_t)(k0 + r) * 256 + nw + c];
        }
        __syncthreads();
#pragma unroll
        for (int kk = 0; kk < 16; ++kk) {
            float av[4];
#pragma unroll
            for (int i = 0; i < 4; ++i) av[i] = As[kk][ti * 4 + i];
            float4 bq = *(const float4*)&Bs[kk][tj * 4];
            float bv4[4] = {bq.x, bq.y, bq.z, bq.w};
#pragma unroll
            for (int i = 0; i < 4; ++i)
#pragma unroll
                for (int j = 0; j < 4; ++j)
                    acc[i][j] = fmaf(av[i], bv4[j], acc[i][j]);
        }
        __syncthreads();
    }

    const size_t hofs = (size_t)M_ * H_;
#pragma unroll
    for (int j = 0; j < 4; ++j) {
        int col = nw + tj * 4 + j;
        float bias = bb[col];
#pragma unroll
        for (int i = 0; i < 4; ++i) {
            int row = m0 + ti * 4 + i;
            float v = acc[i][j] + bias;
            if (isV) out[(size_t)row * 256 + col] = expf(v);     // J_diag
            else     out[hofs + (size_t)row * 256 + col] = v;    // h
        }
    }
}

// ---------------------------------------------------------------------------
extern "C" void kernel_launch(void* const* d_in, const int* in_sizes, int n_in,
                              void* d_out, int out_size)
{
    const float* inputs = (const float*)d_in[0];
    const float* Wi_f   = (const float*)d_in[1];
    const float* bi_f   = (const float*)d_in[2];
    const float* Wh_f   = (const float*)d_in[3];
    const float* bhn_f  = (const float*)d_in[4];
    const float* Wi_b   = (const float*)d_in[5];
    const float* bi_b   = (const float*)d_in[6];
    const float* Wh_b   = (const float*)d_in[7];
    const float* bhn_b  = (const float*)d_in[8];
    const float* Wm     = (const float*)d_in[9];
    const float* bm     = (const float*)d_in[10];
    const float* Wv     = (const float*)d_in[11];
    const float* bv     = (const float*)d_in[12];
    float* out = (float*)d_out;

    (void)in_sizes; (void)n_in; (void)out_size;

    cudaFuncSetAttribute(k_scan, cudaFuncAttributeMaxDynamicSharedMemorySize,
                         SM_SCAN_BYTES);

    // 1) input projections for both directions
    k_xgemm<<<dim3(12, 512, 2), 256>>>(inputs, Wi_f, bi_f, Wi_b, bi_b);
    // 2) clustered bidirectional scan: 16 clusters x 8 CTAs, DSMEM h-exchange
    k_scan<<<128, 256, SM_SCAN_BYTES>>>(Wh_f, bhn_f, Wh_b, bhn_b);
    // 3) heads: mean + exp(log-var)
    k_heads<<<dim3(8, 512), 256>>>(Wm, bm, Wv, bv, out);
}

// round 4
// speedup vs baseline: 1.3975x; 1.3975x over previous
#include <cuda_runtime.h>
#include <cstdint>

#define B_ 8
#define T_ 4096
#define D_ 256
#define H_ 256
#define G_ 768              // 3H
#define M_ (B_ * T_)        // 32768

// Scratch (static device allocations only)
__device__ float g_xg[(size_t)2 * B_ * T_ * G_];       // [dir][b][t][768]
__device__ float g_outc[(size_t)B_ * T_ * 2 * H_];     // [b][t][512]  (fwd | bwd)

__device__ __forceinline__ uint32_t s2u(const void* p) {
    uint32_t a;
    asm("{ .reg .u64 t; cvta.to.shared.u64 t, %1; cvt.u32.u64 %0, t; }"
        : "=r"(a) : "l"(p));
    return a;
}

// ---------------------------------------------------------------------------
// Kernel A: xg[d] = X @ Wi_d + bi_d   X:[32768,256], Wi:[256,768]
// 128x64 tile, 8x4 per thread.
// ---------------------------------------------------------------------------
__global__ void __launch_bounds__(256) k_xgemm(
    const float* __restrict__ X,
    const float* __restrict__ Wi_f, const float* __restrict__ bi_f,
    const float* __restrict__ Wi_b, const float* __restrict__ bi_b)
{
    const int d = blockIdx.z;
    const float* W  = d ? Wi_b : Wi_f;
    const float* bi = d ? bi_b : bi_f;
    float* out = g_xg + (size_t)d * M_ * G_;

    const int m0 = blockIdx.y * 128;
    const int n0 = blockIdx.x * 64;

    __shared__ float As[16][136];   // [k][m], padded (136: 16B-aligned rows)
    __shared__ float Bs[16][64];    // [k][n]

    const int tid = threadIdx.x;
    const int ti = tid >> 4;        // 0..15 -> 8 rows each
    const int tj = tid & 15;        // 0..15 -> 4 cols each

    float acc[8][4];
#pragma unroll
    for (int i = 0; i < 8; ++i)
#pragma unroll
        for (int j = 0; j < 4; ++j) acc[i][j] = 0.f;

    for (int k0 = 0; k0 < D_; k0 += 16) {
#pragma unroll
        for (int p = 0; p < 8; ++p) {
            int idx = tid + p * 256;          // 0..2047
            int r = idx >> 4, c = idx & 15;   // m, k
            As[c][r] = X[(size_t)(m0 + r) * D_ + k0 + c];
        }
#pragma unroll
        for (int p = 0; p < 4; ++p) {
            int idx = tid + p * 256;
            int r = idx >> 6, c = idx & 63;   // k, n
            Bs[r][c] = W[(size_t)(k0 + r) * G_ + n0 + c];
        }
        __syncthreads();
#pragma unroll
        for (int kk = 0; kk < 16; ++kk) {
            float4 a0 = *(const float4*)&As[kk][ti * 8];
            float4 a1 = *(const float4*)&As[kk][ti * 8 + 4];
            float4 bq = *(const float4*)&Bs[kk][tj * 4];
            float av[8] = {a0.x, a0.y, a0.z, a0.w, a1.x, a1.y, a1.z, a1.w};
            float bv4[4] = {bq.x, bq.y, bq.z, bq.w};
#pragma unroll
            for (int i = 0; i < 8; ++i)
#pragma unroll
                for (int j = 0; j < 4; ++j)
                    acc[i][j] = fmaf(av[i], bv4[j], acc[i][j]);
        }
        __syncthreads();
    }

    float4 bb = *(const float4*)&bi[n0 + tj * 4];
#pragma unroll
    for (int i = 0; i < 8; ++i) {
        float4 o;
        o.x = acc[i][0] + bb.x; o.y = acc[i][1] + bb.y;
        o.z = acc[i][2] + bb.z; o.w = acc[i][3] + bb.w;
        *(float4*)&out[(size_t)(m0 + ti * 8 + i) * G_ + n0 + tj * 4] = o;
    }
}

// ---------------------------------------------------------------------------
// Kernel B: clustered bidirectional GRU scan, W in registers, fence-free
// mbarrier release/acquire DSMEM exchange. 16 clusters x 8 CTAs.
// CTA = (dir, batch, hidden-slice of 32 units). Warp = 4 units.
// Lane = kq*4 + j : K-chunk kq (32 of 256), unit j (of warp's 4).
// ---------------------------------------------------------------------------
__global__ void __launch_bounds__(256, 1) __cluster_dims__(8, 1, 1)
k_scan(const float* __restrict__ Wh_f, const float* __restrict__ bhn_f,
       const float* __restrict__ Wh_b, const float* __restrict__ bhn_b)
{
    __shared__ __align__(16) float hbuf[3][288];   // skewed: unit u -> (u>>5)*36 + (u&31)
    __shared__ __align__(8) unsigned long long mbar[3];

    const uint32_t hbuf_a = s2u(hbuf);
    const uint32_t mbar_a = s2u(mbar);

    const int rank = blockIdx.x & 7;               // hidden slice
    const int cid  = blockIdx.x >> 3;
    const int d    = cid >> 3;                     // direction
    const int b    = cid & 7;                      // batch

    const float* Wh  = d ? Wh_b  : Wh_f;
    const float* bhn = d ? bhn_b : bhn_f;

    const int tid  = threadIdx.x;
    const int w    = tid >> 5;
    const int lane = tid & 31;
    const int kq   = lane >> 2;                    // K-chunk (0..7)
    const int j    = lane & 3;                     // unit within warp
    const int unit = rank * 32 + w * 4 + j;        // global hidden unit of this lane's column

    // ---- W slice into registers: 96 floats/lane ----
    float Wr[32], Wz[32], Wn[32];
#pragma unroll
    for (int kk = 0; kk < 32; ++kk) {
        size_t row = (size_t)(kq * 32 + kk) * G_;
        Wr[kk] = __ldg(Wh + row + unit);
        Wz[kk] = __ldg(Wh + row + 256 + unit);
        Wn[kk] = __ldg(Wh + row + 512 + unit);
    }

    for (int i = tid; i < 3 * 288; i += 256) ((float*)hbuf)[i] = 0.f;  // h0 = 0
    if (tid == 0) {
#pragma unroll
        for (int i = 0; i < 3; ++i)
            asm volatile("mbarrier.init.shared.b64 [%0], %1;"
                         :: "r"(mbar_a + i * 8), "r"(64) : "memory");
    }
    __syncthreads();
    asm volatile("barrier.cluster.arrive.aligned;" ::: "memory");
    asm volatile("barrier.cluster.wait.aligned;"   ::: "memory");

    // precomputed remote addresses
    const uint32_t peer = (uint32_t)kq;            // push target CTA (8 peers x 4 units = 32 lanes)
    uint32_t rh;                                    // peer's hbuf base
    asm("mapa.shared::cluster.u32 %0, %1, %2;" : "=r"(rh) : "r"(hbuf_a), "r"(peer));
    const uint32_t sidx = (uint32_t)(rank * 36 + w * 4 + j);  // skewed slot of our pushed unit
    uint32_t rmb = 0;                               // peer mbar base (lanes 0..7)
    if (lane < 8)
        asm("mapa.shared::cluster.u32 %0, %1, %2;" : "=r"(rmb) : "r"(mbar_a), "r"(lane));

    // initial arrives for step 0 (buffer 0 already holds h0 = 0)
    if (lane < 8)
        asm volatile("mbarrier.arrive.release.cluster.shared::cluster.b64 _, [%0];"
                     :: "r"(rmb) : "memory");

    const float bhn_u = (lane < 4) ? bhn[unit] : 0.f;
    const float* xg_base = g_xg + ((size_t)(d * B_ + b)) * T_ * G_;

    // prefetch gi for step 0: lanes 0..11 = (gate = lane>>2, unit j = lane&3)
    float giv = 0.f;
    if (lane < 12) {
        const int t0 = d ? (T_ - 1) : 0;
        giv = __ldg(xg_base + (size_t)t0 * G_ + (lane >> 2) * H_ + rank * 32 + w * 4 + (lane & 3));
    }

    int p = 0;
    unsigned par = 0;

    for (int s = 0; s < T_; ++s) {
        const int t = d ? (T_ - 1 - s) : s;

        // ---- wait for all 64 producer-warp arrivals of step s ----
        asm volatile(
            "{\n\t.reg .pred P;\n\t"
            "LW_%=:\n\t"
            "mbarrier.try_wait.parity.acquire.cluster.shared::cta.b64 P, [%0], %1, 0x989680;\n\t"
            "@P bra.uni LD_%=;\n\t"
            "bra.uni LW_%=;\n\t"
            "LD_%=:\n\t}"
            :: "r"(mbar_a + p * 8), "r"(par) : "memory");

        // ---- 3 dots over this lane's 32-K chunk ----
        const float* hp = &hbuf[p][kq * 36];
        float sr0 = 0.f, sr1 = 0.f, sz0 = 0.f, sz1 = 0.f, sn0 = 0.f, sn1 = 0.f;
#pragma unroll
        for (int q = 0; q < 8; ++q) {
            float4 hv = *(const float4*)(hp + q * 4);
            sr0 = fmaf(Wr[q * 4 + 0], hv.x, sr0);
            sr1 = fmaf(Wr[q * 4 + 1], hv.y, sr1);
            sr0 = fmaf(Wr[q * 4 + 2], hv.z, sr0);
            sr1 = fmaf(Wr[q * 4 + 3], hv.w, sr1);
            sz0 = fmaf(Wz[q * 4 + 0], hv.x, sz0);
            sz1 = fmaf(Wz[q * 4 + 1], hv.y, sz1);
            sz0 = fmaf(Wz[q * 4 + 2], hv.z, sz0);
            sz1 = fmaf(Wz[q * 4 + 3], hv.w, sz1);
            sn0 = fmaf(Wn[q * 4 + 0], hv.x, sn0);
            sn1 = fmaf(Wn[q * 4 + 1], hv.y, sn1);
            sn0 = fmaf(Wn[q * 4 + 2], hv.z, sn0);
            sn1 = fmaf(Wn[q * 4 + 3], hv.w, sn1);
        }
        float sr = sr0 + sr1, sz = sz0 + sz1, sn = sn0 + sn1;
#pragma unroll
        for (int m = 16; m >= 4; m >>= 1) {
            sr += __shfl_xor_sync(0xFFFFFFFFu, sr, m);
            sz += __shfl_xor_sync(0xFFFFFFFFu, sz, m);
            sn += __shfl_xor_sync(0xFFFFFFFFu, sn, m);
        }
        // lanes 0..3 now hold full sums for units w*4 + lane

        float gr = __shfl_sync(0xFFFFFFFFu, giv, j);
        float gz = __shfl_sync(0xFFFFFFFFu, giv, 4 + j);
        float gn = __shfl_sync(0xFFFFFFFFu, giv, 8 + j);

        float hn = 0.f;
        if (lane < 4) {
            float r = 1.f / (1.f + expf(-(gr + sr)));
            float z = 1.f / (1.f + expf(-(gz + sz)));
            float n = tanhf(fmaf(r, sn + bhn_u, gn));
            float hprev = hbuf[p][rank * 36 + w * 4 + lane];
            hn = fmaf(z, hprev - n, n);              // (1-z)*n + z*h
        }

        if (s + 1 < T_) {
            const int pn = (p + 1 == 3) ? 0 : p + 1;

            // push this warp's 4 h values to all 8 peers (1 DSMEM store/lane)
            float val = __shfl_sync(0xFFFFFFFFu, hn, j);
            uint32_t dst = rh + (uint32_t)pn * 1152 + sidx * 4;
            asm volatile("st.shared::cluster.u32 [%0], %1;"
                         :: "r"(dst), "r"(__float_as_uint(val)) : "memory");

            // warp-level release-arrive on peers' next-buffer barrier
            if (lane < 8)
                asm volatile("mbarrier.arrive.release.cluster.shared::cluster.b64 _, [%0];"
                             :: "r"(rmb + (uint32_t)pn * 8) : "memory");

            // prefetch gi for step s+1 (overlaps next wait)
            if (lane < 12) {
                const int tn = d ? (T_ - 2 - s) : (s + 1);
                giv = __ldg(xg_base + (size_t)tn * G_ +
                            (lane >> 2) * H_ + rank * 32 + w * 4 + (lane & 3));
            }
        }

        // off critical path: sequence output
        if (lane < 4)
            g_outc[((size_t)b * T_ + t) * (2 * H_) + d * H_ + rank * 32 + w * 4 + lane] = hn;

        if (++p == 3) { p = 0; par ^= 1u; }
    }
}

// ---------------------------------------------------------------------------
// Kernel C: heads. out_combined [32768,512] @ (Wm|Wv) [512,256] + bias.
// 128x64 tile, 8x4 per thread. J=exp(var) -> d_out[0:M*H); h -> d_out[M*H:).
// ---------------------------------------------------------------------------
__global__ void __launch_bounds__(256) k_heads(
    const float* __restrict__ Wm, const float* __restrict__ bm,
    const float* __restrict__ Wv, const float* __restrict__ bv,
    float* __restrict__ out)
{
    const int n0 = blockIdx.x * 64;        // 0..511
    const int m0 = blockIdx.y * 128;
    const bool isV = (n0 >= 256);
    const float* W  = isV ? Wv : Wm;       // [512][256]
    const float* bb = isV ? bv : bm;
    const int nw = n0 & 255;

    __shared__ float As[16][136];
    __shared__ float Bs[16][64];

    const int tid = threadIdx.x;
    const int ti = tid >> 4, tj = tid & 15;

    float acc[8][4];
#pragma unroll
    for (int i = 0; i < 8; ++i)
#pragma unroll
        for (int j = 0; j < 4; ++j) acc[i][j] = 0.f;

    for (int k0 = 0; k0 < 512; k0 += 16) {
#pragma unroll
        for (int p = 0; p < 8; ++p) {
            int idx = tid + p * 256;
            int r = idx >> 4, c = idx & 15;
            As[c][r] = g_outc[(size_t)(m0 + r) * 512 + k0 + c];
        }
#pragma unroll
        for (int p = 0; p < 4; ++p) {
            int idx = tid + p * 256;
            int r = idx >> 6, c = idx & 63;
            Bs[r][c] = W[(size_t)(k0 + r) * 256 + nw + c];
        }
        __syncthreads();
#pragma unroll
        for (int kk = 0; kk < 16; ++kk) {
            float4 a0 = *(const float4*)&As[kk][ti * 8];
            float4 a1 = *(const float4*)&As[kk][ti * 8 + 4];
            float4 bq = *(const float4*)&Bs[kk][tj * 4];
            float av[8] = {a0.x, a0.y, a0.z, a0.w, a1.x, a1.y, a1.z, a1.w};
            float bv4[4] = {bq.x, bq.y, bq.z, bq.w};
#pragma unroll
            for (int i = 0; i < 8; ++i)
#pragma unroll
                for (int jj = 0; jj < 4; ++jj)
                    acc[i][jj] = fmaf(av[i], bv4[jj], acc[i][jj]);
        }
        __syncthreads();
    }

    const size_t hofs = (size_t)M_ * H_;   // h in second half
    float4 bb4 = *(const float4*)&bb[nw + tj * 4];
#pragma unroll
    for (int i = 0; i < 8; ++i) {
        int row = m0 + ti * 8 + i;
        float4 v;
        v.x = acc[i][0] + bb4.x; v.y = acc[i][1] + bb4.y;
        v.z = acc[i][2] + bb4.z; v.w = acc[i][3] + bb4.w;
        if (isV) {
            v.x = expf(v.x); v.y = expf(v.y); v.z = expf(v.z); v.w = expf(v.w);
            *(float4*)&out[(size_t)row * 256 + nw + tj * 4] = v;        // J_diag
        } else {
            *(float4*)&out[hofs + (size_t)row * 256 + nw + tj * 4] = v; // h
        }
    }
}

// ---------------------------------------------------------------------------
extern "C" void kernel_launch(void* const* d_in, const int* in_sizes, int n_in,
                              void* d_out, int out_size)
{
    const float* inputs = (const float*)d_in[0];
    const float* Wi_f   = (const float*)d_in[1];
    const float* bi_f   = (const float*)d_in[2];
    const float* Wh_f   = (const float*)d_in[3];
    const float* bhn_f  = (const float*)d_in[4];
    const float* Wi_b   = (const float*)d_in[5];
    const float* bi_b   = (const float*)d_in[6];
    const float* Wh_b   = (const float*)d_in[7];
    const float* bhn_b  = (const float*)d_in[8];
    const float* Wm     = (const float*)d_in[9];
    const float* bm     = (const float*)d_in[10];
    const float* Wv     = (const float*)d_in[11];
    const float* bv     = (const float*)d_in[12];
    float* out = (float*)d_out;

    (void)in_sizes; (void)n_in; (void)out_size;

    // 1) input projections for both directions
    k_xgemm<<<dim3(12, 256, 2), 256>>>(inputs, Wi_f, bi_f, Wi_b, bi_b);
    // 2) clustered bidirectional scan: 16 clusters x 8 CTAs, fence-free DSMEM
    k_scan<<<128, 256>>>(Wh_f, bhn_f, Wh_b, bhn_b);
    // 3) heads: mean + exp(log-var)
    k_heads<<<dim3(8, 256), 256>>>(Wm, bm, Wv, bv, out);
}

// round 5
// speedup vs baseline: 1.4026x; 1.0037x over previous
#include <cuda_runtime.h>
#include <cstdint>

#define B_ 8
#define T_ 4096
#define D_ 256
#define H_ 256
#define G_ 768              // 3H
#define M_ (B_ * T_)        // 32768

// Scratch (static device allocations only)
__device__ float g_xg[(size_t)2 * B_ * T_ * G_];       // [dir][b][t][768]
__device__ float g_outc[(size_t)B_ * T_ * 2 * H_];     // [b][t][512]  (fwd | bwd)

__device__ __forceinline__ uint32_t s2u(const void* p) {
    uint32_t a;
    asm("{ .reg .u64 t; cvta.to.shared.u64 t, %1; cvt.u32.u64 %0, t; }"
        : "=r"(a) : "l"(p));
    return a;
}
__device__ __forceinline__ unsigned long long ffma2(
    unsigned long long a, unsigned long long b, unsigned long long c) {
    unsigned long long d;
    asm("fma.rn.f32x2 %0, %1, %2, %3;" : "=l"(d) : "l"(a), "l"(b), "l"(c));
    return d;
}
__device__ __forceinline__ unsigned long long fadd2(
    unsigned long long a, unsigned long long b) {
    unsigned long long d;
    asm("add.rn.f32x2 %0, %1, %2;" : "=l"(d) : "l"(a), "l"(b));
    return d;
}
__device__ __forceinline__ unsigned long long pack2(float lo, float hi) {
    unsigned long long r;
    asm("mov.b64 %0, {%1, %2};" : "=l"(r)
        : "r"(__float_as_uint(lo)), "r"(__float_as_uint(hi)));
    return r;
}
__device__ __forceinline__ float sum2(unsigned long long a) {
    uint32_t lo, hi;
    asm("mov.b64 {%0, %1}, %2;" : "=r"(lo), "=r"(hi) : "l"(a));
    return __uint_as_float(lo) + __uint_as_float(hi);
}
__device__ __forceinline__ unsigned ldacq_sh(uint32_t a) {
    unsigned v;
    asm volatile("ld.acquire.cluster.shared::cta.u32 %0, [%1];"
                 : "=r"(v) : "r"(a) : "memory");
    return v;
}

// ---------------------------------------------------------------------------
// Kernel A: xg[d] = X @ Wi_d + bi_d   X:[32768,256], Wi:[256,768]
// ---------------------------------------------------------------------------
__global__ void __launch_bounds__(256) k_xgemm(
    const float* __restrict__ X,
    const float* __restrict__ Wi_f, const float* __restrict__ bi_f,
    const float* __restrict__ Wi_b, const float* __restrict__ bi_b)
{
    const int d = blockIdx.z;
    const float* W  = d ? Wi_b : Wi_f;
    const float* bi = d ? bi_b : bi_f;
    float* out = g_xg + (size_t)d * M_ * G_;

    const int m0 = blockIdx.y * 128;
    const int n0 = blockIdx.x * 64;

    __shared__ float As[16][136];
    __shared__ float Bs[16][64];

    const int tid = threadIdx.x;
    const int ti = tid >> 4;
    const int tj = tid & 15;

    float acc[8][4];
#pragma unroll
    for (int i = 0; i < 8; ++i)
#pragma unroll
        for (int j = 0; j < 4; ++j) acc[i][j] = 0.f;

    for (int k0 = 0; k0 < D_; k0 += 16) {
#pragma unroll
        for (int p = 0; p < 8; ++p) {
            int idx = tid + p * 256;
            int r = idx >> 4, c = idx & 15;
            As[c][r] = X[(size_t)(m0 + r) * D_ + k0 + c];
        }
#pragma unroll
        for (int p = 0; p < 4; ++p) {
            int idx = tid + p * 256;
            int r = idx >> 6, c = idx & 63;
            Bs[r][c] = W[(size_t)(k0 + r) * G_ + n0 + c];
        }
        __syncthreads();
#pragma unroll
        for (int kk = 0; kk < 16; ++kk) {
            float4 a0 = *(const float4*)&As[kk][ti * 8];
            float4 a1 = *(const float4*)&As[kk][ti * 8 + 4];
            float4 bq = *(const float4*)&Bs[kk][tj * 4];
            float av[8] = {a0.x, a0.y, a0.z, a0.w, a1.x, a1.y, a1.z, a1.w};
            float bv4[4] = {bq.x, bq.y, bq.z, bq.w};
#pragma unroll
            for (int i = 0; i < 8; ++i)
#pragma unroll
                for (int j = 0; j < 4; ++j)
                    acc[i][j] = fmaf(av[i], bv4[j], acc[i][j]);
        }
        __syncthreads();
    }

    float4 bb = *(const float4*)&bi[n0 + tj * 4];
#pragma unroll
    for (int i = 0; i < 8; ++i) {
        float4 o;
        o.x = acc[i][0] + bb.x; o.y = acc[i][1] + bb.y;
        o.z = acc[i][2] + bb.z; o.w = acc[i][3] + bb.w;
        *(float4*)&out[(size_t)(m0 + ti * 8 + i) * G_ + n0 + tj * 4] = o;
    }
}

// ---------------------------------------------------------------------------
// Kernel B: clustered bidirectional GRU scan.
// 16 clusters x 8 CTAs; CTA = (dir, batch, 32-unit hidden slice).
// Signaling: monotonic epoch flags (plain release stores), NO atomics,
// NO mbarriers, NO fences. Dots use packed fma.rn.f32x2.
// ---------------------------------------------------------------------------
__global__ void __launch_bounds__(256, 1) __cluster_dims__(8, 1, 1)
k_scan(const float* __restrict__ Wh_f, const float* __restrict__ bhn_f,
       const float* __restrict__ Wh_b, const float* __restrict__ bhn_b)
{
    __shared__ __align__(16) float hbuf[3][288];   // unit u -> (u>>5)*36 + (u&31)
    __shared__ __align__(16) unsigned flags[64];   // [producer_cta][producer_warp]

    const uint32_t hbuf_a = s2u(hbuf);
    const uint32_t flag_a = s2u(flags);

    const int rank = blockIdx.x & 7;               // hidden slice
    const int cid  = blockIdx.x >> 3;
    const int d    = cid >> 3;                     // direction
    const int b    = cid & 7;                      // batch

    const float* Wh  = d ? Wh_b  : Wh_f;
    const float* bhn = d ? bhn_b : bhn_f;

    const int tid  = threadIdx.x;
    const int w    = tid >> 5;
    const int lane = tid & 31;
    const int kq   = lane >> 2;                    // K-chunk (0..7)
    const int j    = lane & 3;                     // unit within warp
    const int unit = rank * 32 + w * 4 + j;

    // ---- W slice into packed f32x2 registers: 48 x b64 per lane ----
    unsigned long long Wr2[16], Wz2[16], Wn2[16];
#pragma unroll
    for (int kk = 0; kk < 16; ++kk) {
        size_t r0 = (size_t)(kq * 32 + kk * 2) * G_;
        size_t r1 = r0 + G_;
        Wr2[kk] = pack2(__ldg(Wh + r0 + unit),       __ldg(Wh + r1 + unit));
        Wz2[kk] = pack2(__ldg(Wh + r0 + 256 + unit), __ldg(Wh + r1 + 256 + unit));
        Wn2[kk] = pack2(__ldg(Wh + r0 + 512 + unit), __ldg(Wh + r1 + 512 + unit));
    }

    for (int i = tid; i < 3 * 288; i += 256) ((float*)hbuf)[i] = 0.f;  // h0 = 0
    if (tid < 64) flags[tid] = 0u;
    __syncthreads();
    asm volatile("barrier.cluster.arrive.aligned;" ::: "memory");
    asm volatile("barrier.cluster.wait.aligned;"   ::: "memory");

    // precomputed remote addresses (lanes 0..7: peer = lane)
    uint32_t rh = 0, rf = 0;
    if (lane < 8) {
        asm("mapa.shared::cluster.u32 %0, %1, %2;" : "=r"(rh) : "r"(hbuf_a), "r"(lane));
        asm("mapa.shared::cluster.u32 %0, %1, %2;" : "=r"(rf) : "r"(flag_a), "r"(lane));
        rh += (uint32_t)(rank * 144 + w * 16);     // byte slot of our 4 units (16B aligned)
        rf += (uint32_t)(rank * 8 + w) * 4;        // our flag word
    }
    const uint32_t fa0 = flag_a + (uint32_t)(kq * 8 + j) * 4;
    const uint32_t fa1 = flag_a + (uint32_t)(kq * 8 + 4 + j) * 4;

    const float bhn_u = (lane < 4) ? bhn[unit] : 0.f;
    const float* xg_base = g_xg + ((size_t)(d * B_ + b)) * T_ * G_;

    // prefetch gi for step 0
    float giv = 0.f;
    if (lane < 12) {
        const int t0 = d ? (T_ - 1) : 0;
        giv = __ldg(xg_base + (size_t)t0 * G_ + (lane >> 2) * H_ + rank * 32 + w * 4 + (lane & 3));
    }

    float hprev = 0.f;     // lanes 0..3: our own unit's previous h
    int p = 0;

    for (int s = 0; s < T_; ++s) {
        const int t = d ? (T_ - 1 - s) : s;
        const unsigned us = (unsigned)s;

        // ---- wait: all 64 producer flags >= s (collectively via warp vote) ----
        for (;;) {
            unsigned f0 = ldacq_sh(fa0);
            unsigned f1 = ldacq_sh(fa1);
            if (__all_sync(0xFFFFFFFFu, (f0 >= us) && (f1 >= us))) break;
        }

        // ---- 3 packed dots over this lane's 32-K chunk ----
        const float* hp = &hbuf[p][kq * 36];
        unsigned long long ar0 = 0, ar1 = 0, az0 = 0, az1 = 0, an0 = 0, an1 = 0;
#pragma unroll
        for (int q = 0; q < 8; ++q) {
            ulonglong2 hv = *(const ulonglong2*)(hp + q * 4);
            ar0 = ffma2(Wr2[q * 2],     hv.x, ar0);
            ar1 = ffma2(Wr2[q * 2 + 1], hv.y, ar1);
            az0 = ffma2(Wz2[q * 2],     hv.x, az0);
            az1 = ffma2(Wz2[q * 2 + 1], hv.y, az1);
            an0 = ffma2(Wn2[q * 2],     hv.x, an0);
            an1 = ffma2(Wn2[q * 2 + 1], hv.y, an1);
        }
        float sr = sum2(fadd2(ar0, ar1));
        float sz = sum2(fadd2(az0, az1));
        float sn = sum2(fadd2(an0, an1));
#pragma unroll
        for (int m = 16; m >= 4; m >>= 1) {
            sr += __shfl_xor_sync(0xFFFFFFFFu, sr, m);
            sz += __shfl_xor_sync(0xFFFFFFFFu, sz, m);
            sn += __shfl_xor_sync(0xFFFFFFFFu, sn, m);
        }
        // lanes 0..3 hold full sums for units w*4 + lane

        float gr = __shfl_sync(0xFFFFFFFFu, giv, j);
        float gz = __shfl_sync(0xFFFFFFFFu, giv, 4 + j);
        float gn = __shfl_sync(0xFFFFFFFFu, giv, 8 + j);

        float hn = 0.f;
        if (lane < 4) {
            float r = 1.f / (1.f + expf(-(gr + sr)));
            float z = 1.f / (1.f + expf(-(gz + sz)));
            float n = tanhf(fmaf(r, sn + bhn_u, gn));
            hn = fmaf(z, hprev - n, n);              // (1-z)*n + z*h
            hprev = hn;
        }

        if (s + 1 < T_) {
            const int pn = (p + 1 == 3) ? 0 : p + 1;

            // gather this warp's 4 h values into a float4 (all lanes)
            float4 hv;
            hv.x = __shfl_sync(0xFFFFFFFFu, hn, 0);
            hv.y = __shfl_sync(0xFFFFFFFFu, hn, 1);
            hv.z = __shfl_sync(0xFFFFFFFFu, hn, 2);
            hv.w = __shfl_sync(0xFFFFFFFFu, hn, 3);

            if (lane < 8) {
                // one 16B data store + one release flag store per peer
                uint32_t dst = rh + (uint32_t)pn * 1152;
                asm volatile("st.shared::cluster.v4.b32 [%0], {%1, %2, %3, %4};"
                             :: "r"(dst),
                                "r"(__float_as_uint(hv.x)), "r"(__float_as_uint(hv.y)),
                                "r"(__float_as_uint(hv.z)), "r"(__float_as_uint(hv.w))
                             : "memory");
                asm volatile("st.release.cluster.shared::cluster.u32 [%0], %1;"
                             :: "r"(rf), "r"((unsigned)(s + 1)) : "memory");
            }

            // prefetch gi for step s+1 (overlaps next wait)
            if (lane < 12) {
                const int tn = d ? (T_ - 2 - s) : (s + 1);
                giv = __ldg(xg_base + (size_t)tn * G_ +
                            (lane >> 2) * H_ + rank * 32 + w * 4 + (lane & 3));
            }
            p = pn;
        }

        // off critical path: sequence output
        if (lane < 4)
            g_outc[((size_t)b * T_ + t) * (2 * H_) + d * H_ + rank * 32 + w * 4 + lane] = hn;
    }
}

// ---------------------------------------------------------------------------
// Kernel C: heads. out_combined [32768,512] @ (Wm|Wv) [512,256] + bias.
// ---------------------------------------------------------------------------
__global__ void __launch_bounds__(256) k_heads(
    const float* __restrict__ Wm, const float* __restrict__ bm,
    const float* __restrict__ Wv, const float* __restrict__ bv,
    float* __restrict__ out)
{
    const int n0 = blockIdx.x * 64;
    const int m0 = blockIdx.y * 128;
    const bool isV = (n0 >= 256);
    const float* W  = isV ? Wv : Wm;
    const float* bb = isV ? bv : bm;
    const int nw = n0 & 255;

    __shared__ float As[16][136];
    __shared__ float Bs[16][64];

    const int tid = threadIdx.x;
    const int ti = tid >> 4, tj = tid & 15;

    float acc[8][4];
#pragma unroll
    for (int i = 0; i < 8; ++i)
#pragma unroll
        for (int j = 0; j < 4; ++j) acc[i][j] = 0.f;

    for (int k0 = 0; k0 < 512; k0 += 16) {
#pragma unroll
        for (int p = 0; p < 8; ++p) {
            int idx = tid + p * 256;
            int r = idx >> 4, c = idx & 15;
            As[c][r] = g_outc[(size_t)(m0 + r) * 512 + k0 + c];
        }
#pragma unroll
        for (int p = 0; p < 4; ++p) {
            int idx = tid + p * 256;
            int r = idx >> 6, c = idx & 63;
            Bs[r][c] = W[(size_t)(k0 + r) * 256 + nw + c];
        }
        __syncthreads();
#pragma unroll
        for (int kk = 0; kk < 16; ++kk) {
            float4 a0 = *(const float4*)&As[kk][ti * 8];
            float4 a1 = *(const float4*)&As[kk][ti * 8 + 4];
            float4 bq = *(const float4*)&Bs[kk][tj * 4];
            float av[8] = {a0.x, a0.y, a0.z, a0.w, a1.x, a1.y, a1.z, a1.w};
            float bv4[4] = {bq.x, bq.y, bq.z, bq.w};
#pragma unroll
            for (int i = 0; i < 8; ++i)
#pragma unroll
                for (int jj = 0; jj < 4; ++jj)
                    acc[i][jj] = fmaf(av[i], bv4[jj], acc[i][jj]);
        }
        __syncthreads();
    }

    const size_t hofs = (size_t)M_ * H_;
    float4 bb4 = *(const float4*)&bb[nw + tj * 4];
#pragma unroll
    for (int i = 0; i < 8; ++i) {
        int row = m0 + ti * 8 + i;
        float4 v;
        v.x = acc[i][0] + bb4.x; v.y = acc[i][1] + bb4.y;
        v.z = acc[i][2] + bb4.z; v.w = acc[i][3] + bb4.w;
        if (isV) {
            v.x = expf(v.x); v.y = expf(v.y); v.z = expf(v.z); v.w = expf(v.w);
            *(float4*)&out[(size_t)row * 256 + nw + tj * 4] = v;        // J_diag
        } else {
            *(float4*)&out[hofs + (size_t)row * 256 + nw + tj * 4] = v; // h
        }
    }
}

// ---------------------------------------------------------------------------
extern "C" void kernel_launch(void* const* d_in, const int* in_sizes, int n_in,
                              void* d_out, int out_size)
{
    const float* inputs = (const float*)d_in[0];
    const float* Wi_f   = (const float*)d_in[1];
    const float* bi_f   = (const float*)d_in[2];
    const float* Wh_f   = (const float*)d_in[3];
    const float* bhn_f  = (const float*)d_in[4];
    const float* Wi_b   = (const float*)d_in[5];
    const float* bi_b   = (const float*)d_in[6];
    const float* Wh_b   = (const float*)d_in[7];
    const float* bhn_b  = (const float*)d_in[8];
    const float* Wm     = (const float*)d_in[9];
    const float* bm     = (const float*)d_in[10];
    const float* Wv     = (const float*)d_in[11];
    const float* bv     = (const float*)d_in[12];
    float* out = (float*)d_out;

    (void)in_sizes; (void)n_in; (void)out_size;

    k_xgemm<<<dim3(12, 256, 2), 256>>>(inputs, Wi_f, bi_f, Wi_b, bi_b);
    k_scan<<<128, 256>>>(Wh_f, bhn_f, Wh_b, bhn_b);
    k_heads<<<dim3(8, 256), 256>>>(Wm, bm, Wv, bv, out);
}

// round 6
// speedup vs baseline: 1.4311x; 1.0203x over previous
#include <cuda_runtime.h>
#include <cstdint>

#define B_ 8
#define T_ 4096
#define D_ 256
#define H_ 256
#define G_ 768              // 3H
#define M_ (B_ * T_)        // 32768

// Scratch (static device allocations only)
// xg layout (scan-permuted): [d][b][t][rank(8)][w(8)][12]  (12 = gate*4 + j)
__device__ float g_xg[(size_t)2 * B_ * T_ * G_];
__device__ float g_outc[(size_t)B_ * T_ * 2 * H_];     // [b][t][512]  (fwd | bwd)

typedef unsigned long long ull;

__device__ __forceinline__ uint32_t s2u(const void* p) {
    uint32_t a;
    asm("{ .reg .u64 t; cvta.to.shared.u64 t, %1; cvt.u32.u64 %0, t; }"
        : "=r"(a) : "l"(p));
    return a;
}
__device__ __forceinline__ ull ffma2(ull a, ull b, ull c) {
    ull d;
    asm("fma.rn.f32x2 %0, %1, %2, %3;" : "=l"(d) : "l"(a), "l"(b), "l"(c));
    return d;
}
__device__ __forceinline__ ull fadd2(ull a, ull b) {
    ull d;
    asm("add.rn.f32x2 %0, %1, %2;" : "=l"(d) : "l"(a), "l"(b));
    return d;
}
__device__ __forceinline__ ull pack2(float lo, float hi) {
    ull r;
    asm("mov.b64 %0, {%1, %2};" : "=l"(r)
        : "r"(__float_as_uint(lo)), "r"(__float_as_uint(hi)));
    return r;
}
__device__ __forceinline__ void unpack2(ull a, float& lo, float& hi) {
    uint32_t l, h;
    asm("mov.b64 {%0, %1}, %2;" : "=r"(l), "=r"(h) : "l"(a));
    lo = __uint_as_float(l); hi = __uint_as_float(h);
}
__device__ __forceinline__ float sum2(ull a) {
    float lo, hi; unpack2(a, lo, hi); return lo + hi;
}
__device__ __forceinline__ unsigned ldacq_sh(uint32_t a) {
    unsigned v;
    asm volatile("ld.acquire.cluster.shared::cta.u32 %0, [%1];"
                 : "=r"(v) : "r"(a) : "memory");
    return v;
}

// ---------------------------------------------------------------------------
// Kernel A: xg[d] = X @ Wi_d + bi_d   X:[32768,256], Wi:[256,768]
// FFMA2 inner loop (B duplicated as f32x2 pairs in smem). Output permuted
// to scan layout: col n -> rank*96 + w*12 + gate*4 + j.
// ---------------------------------------------------------------------------
__global__ void __launch_bounds__(256) k_xgemm(
    const float* __restrict__ X,
    const float* __restrict__ Wi_f, const float* __restrict__ bi_f,
    const float* __restrict__ Wi_b, const float* __restrict__ bi_b)
{
    const int d = blockIdx.z;
    const float* W  = d ? Wi_b : Wi_f;
    const float* bi = d ? bi_b : bi_f;
    float* out = g_xg + (size_t)d * M_ * G_;

    const int m0 = blockIdx.y * 128;
    const int n0 = blockIdx.x * 64;

    __shared__ __align__(16) float As[16][136];  // [k][m]
    __shared__ __align__(16) ull   Bs2[16][64];  // [k][n] duplicated pairs

    const int tid = threadIdx.x;
    const int ti = tid >> 4;        // 8 rows (4 row-pairs)
    const int tj = tid & 15;        // 4 cols

    ull acc2[4][4];
#pragma unroll
    for (int i = 0; i < 4; ++i)
#pragma unroll
        for (int j = 0; j < 4; ++j) acc2[i][j] = 0ull;

    for (int k0 = 0; k0 < D_; k0 += 16) {
#pragma unroll
        for (int p = 0; p < 8; ++p) {
            int idx = tid + p * 256;
            int r = idx >> 4, c = idx & 15;
            As[c][r] = X[(size_t)(m0 + r) * D_ + k0 + c];
        }
#pragma unroll
        for (int p = 0; p < 4; ++p) {
            int idx = tid + p * 256;
            int r = idx >> 6, c = idx & 63;
            float bv = W[(size_t)(k0 + r) * G_ + n0 + c];
            Bs2[r][c] = pack2(bv, bv);
        }
        __syncthreads();
#pragma unroll
        for (int kk = 0; kk < 16; ++kk) {
            // A as natural pairs: 8 floats = 4 x f32x2
            ull ap[4];
            const ull* arow = (const ull*)&As[kk][ti * 8];
            ap[0] = arow[0]; ap[1] = arow[1]; ap[2] = arow[2]; ap[3] = arow[3];
            ull bd[4];
            const ull* brow = &Bs2[kk][tj * 4];
            bd[0] = brow[0]; bd[1] = brow[1]; bd[2] = brow[2]; bd[3] = brow[3];
#pragma unroll
            for (int i = 0; i < 4; ++i)
#pragma unroll
                for (int j = 0; j < 4; ++j)
                    acc2[i][j] = ffma2(ap[i], bd[j], acc2[i][j]);
        }
        __syncthreads();
    }

    // permuted store
    const int n = n0 + tj * 4;
    const int g = n >> 8, u = n & 255;
    const int pos = (u >> 5) * 96 + ((u >> 2) & 7) * 12 + g * 4;
    float4 bb = *(const float4*)&bi[n];
#pragma unroll
    for (int i = 0; i < 4; ++i) {
        float l0, h0;
        float4 o0, o1;
        unpack2(acc2[i][0], o0.x, o1.x);
        unpack2(acc2[i][1], o0.y, o1.y);
        unpack2(acc2[i][2], o0.z, o1.z);
        unpack2(acc2[i][3], o0.w, o1.w);
        (void)l0; (void)h0;
        o0.x += bb.x; o0.y += bb.y; o0.z += bb.z; o0.w += bb.w;
        o1.x += bb.x; o1.y += bb.y; o1.z += bb.z; o1.w += bb.w;
        *(float4*)&out[(size_t)(m0 + ti * 8 + i * 2)     * G_ + pos] = o0;
        *(float4*)&out[(size_t)(m0 + ti * 8 + i * 2 + 1) * G_ + pos] = o1;
    }
}

// ---------------------------------------------------------------------------
// Kernel B: clustered bidirectional GRU scan (16 clusters x 8 CTAs).
// Epoch-flag DSMEM exchange, coalesced xg reads (48B/warp, 2-step prefetch),
// g_outc staged in smem + flushed coalesced every 8 steps.
// ---------------------------------------------------------------------------
__global__ void __launch_bounds__(256, 1) __cluster_dims__(8, 1, 1)
k_scan(const float* __restrict__ Wh_f, const float* __restrict__ bhn_f,
       const float* __restrict__ Wh_b, const float* __restrict__ bhn_b)
{
    __shared__ __align__(16) float hbuf[3][288];   // unit u -> (u>>5)*36 + (u&31)
    __shared__ __align__(16) unsigned flags[64];   // [producer_cta][producer_warp]
    __shared__ __align__(16) float hist[8][32];    // 8-step output staging

    const uint32_t hbuf_a = s2u(hbuf);
    const uint32_t flag_a = s2u(flags);

    const int rank = blockIdx.x & 7;
    const int cid  = blockIdx.x >> 3;
    const int d    = cid >> 3;
    const int b    = cid & 7;

    const float* Wh  = d ? Wh_b  : Wh_f;
    const float* bhn = d ? bhn_b : bhn_f;

    const int tid  = threadIdx.x;
    const int w    = tid >> 5;
    const int lane = tid & 31;
    const int kq   = lane >> 2;
    const int j    = lane & 3;
    const int unit = rank * 32 + w * 4 + j;

    // W slice into packed f32x2 registers
    ull Wr2[16], Wz2[16], Wn2[16];
#pragma unroll
    for (int kk = 0; kk < 16; ++kk) {
        size_t r0 = (size_t)(kq * 32 + kk * 2) * G_;
        size_t r1 = r0 + G_;
        Wr2[kk] = pack2(__ldg(Wh + r0 + unit),       __ldg(Wh + r1 + unit));
        Wz2[kk] = pack2(__ldg(Wh + r0 + 256 + unit), __ldg(Wh + r1 + 256 + unit));
        Wn2[kk] = pack2(__ldg(Wh + r0 + 512 + unit), __ldg(Wh + r1 + 512 + unit));
    }

    for (int i = tid; i < 3 * 288; i += 256) ((float*)hbuf)[i] = 0.f;  // h0 = 0
    if (tid < 64) flags[tid] = 0u;
    __syncthreads();
    asm volatile("barrier.cluster.arrive.aligned;" ::: "memory");
    asm volatile("barrier.cluster.wait.aligned;"   ::: "memory");

    uint32_t rh = 0, rf = 0;
    if (lane < 8) {
        asm("mapa.shared::cluster.u32 %0, %1, %2;" : "=r"(rh) : "r"(hbuf_a), "r"(lane));
        asm("mapa.shared::cluster.u32 %0, %1, %2;" : "=r"(rf) : "r"(flag_a), "r"(lane));
        rh += (uint32_t)(rank * 144 + w * 16);
        rf += (uint32_t)(rank * 8 + w) * 4;
    }
    const uint32_t fa0 = flag_a + (uint32_t)(kq * 8 + j) * 4;
    const uint32_t fa1 = flag_a + (uint32_t)(kq * 8 + 4 + j) * 4;

    const float bhn_u = bhn[unit];
    // permuted xg: [t][rank][w][12], this warp's block:
    const float* xgp = g_xg + ((size_t)(d * B_ + b)) * T_ * G_ + rank * 96 + w * 12;

    // 2-deep gi prefetch (lanes 0..11, contiguous 48B per warp)
    float giv = 0.f, givn = 0.f;
    if (lane < 12) {
        const int t0 = d ? (T_ - 1) : 0;
        const int t1 = d ? (T_ - 2) : 1;
        giv  = __ldg(xgp + (size_t)t0 * G_ + lane);
        givn = __ldg(xgp + (size_t)t1 * G_ + lane);
    }

    float hprev = 0.f;     // all lanes mirror their j-unit's h
    int p = 0;

    for (int s = 0; s < T_; ++s) {
        const int t = d ? (T_ - 1 - s) : s;
        const unsigned us = (unsigned)s;

        // wait: all 64 producer flags >= s
        for (;;) {
            unsigned f0 = ldacq_sh(fa0);
            unsigned f1 = ldacq_sh(fa1);
            if (__all_sync(0xFFFFFFFFu, (f0 >= us) && (f1 >= us))) break;
        }

        // 3 packed dots over this lane's 32-K chunk
        const float* hp = &hbuf[p][kq * 36];
        ull ar0 = 0, ar1 = 0, az0 = 0, az1 = 0, an0 = 0, an1 = 0;
#pragma unroll
        for (int q = 0; q < 8; ++q) {
            ulonglong2 hv2 = *(const ulonglong2*)(hp + q * 4);
            ar0 = ffma2(Wr2[q * 2],     hv2.x, ar0);
            ar1 = ffma2(Wr2[q * 2 + 1], hv2.y, ar1);
            az0 = ffma2(Wz2[q * 2],     hv2.x, az0);
            az1 = ffma2(Wz2[q * 2 + 1], hv2.y, az1);
            an0 = ffma2(Wn2[q * 2],     hv2.x, an0);
            an1 = ffma2(Wn2[q * 2 + 1], hv2.y, an1);
        }
        float sr = sum2(fadd2(ar0, ar1));
        float sz = sum2(fadd2(az0, az1));
        float sn = sum2(fadd2(an0, an1));
#pragma unroll
        for (int m = 16; m >= 4; m >>= 1) {
            sr += __shfl_xor_sync(0xFFFFFFFFu, sr, m);
            sz += __shfl_xor_sync(0xFFFFFFFFu, sz, m);
            sn += __shfl_xor_sync(0xFFFFFFFFu, sn, m);
        }

        float gr = __shfl_sync(0xFFFFFFFFu, giv, j);
        float gz = __shfl_sync(0xFFFFFFFFu, giv, 4 + j);
        float gn = __shfl_sync(0xFFFFFFFFu, giv, 8 + j);

        // gates on ALL lanes (every lane has its j's sums after xor-reduce)
        {
            float r = 1.f / (1.f + expf(-(gr + sr)));
            float z = 1.f / (1.f + expf(-(gz + sz)));
            float n = tanhf(fmaf(r, sn + bhn_u, gn));
            hprev = fmaf(z, hprev - n, n);           // h_new
        }
        if (lane < 4) hist[s & 7][w * 4 + lane] = hprev;

        if (s + 1 < T_) {
            const int pn = (p + 1 == 3) ? 0 : p + 1;

            float4 hv;
            hv.x = __shfl_sync(0xFFFFFFFFu, hprev, 0);
            hv.y = __shfl_sync(0xFFFFFFFFu, hprev, 1);
            hv.z = __shfl_sync(0xFFFFFFFFu, hprev, 2);
            hv.w = __shfl_sync(0xFFFFFFFFu, hprev, 3);

            if (lane < 8) {
                uint32_t dst = rh + (uint32_t)pn * 1152;
                asm volatile("st.shared::cluster.v4.b32 [%0], {%1, %2, %3, %4};"
                             :: "r"(dst),
                                "r"(__float_as_uint(hv.x)), "r"(__float_as_uint(hv.y)),
                                "r"(__float_as_uint(hv.z)), "r"(__float_as_uint(hv.w))
                             : "memory");
                asm volatile("st.release.cluster.shared::cluster.u32 [%0], %1;"
                             :: "r"(rf), "r"((unsigned)(s + 1)) : "memory");
            }

            // prefetch gi for step s+2 (2-deep pipeline)
            giv = givn;
            if (lane < 12 && s + 2 < T_) {
                const int tn = d ? (T_ - 3 - s) : (s + 2);
                givn = __ldg(xgp + (size_t)tn * G_ + lane);
            }
            p = pn;
        }

        // coalesced 8-step output flush (off the release path)
        if ((s & 7) == 7) {
            __syncthreads();
            const int s0 = s - 7 + w;
            const int tw = d ? (T_ - 1 - s0) : s0;
            g_outc[((size_t)b * T_ + tw) * 512 + d * 256 + rank * 32 + lane] =
                hist[w][lane];
            __syncthreads();
        }
    }
}

// ---------------------------------------------------------------------------
// Kernel C: heads. out_combined [32768,512] @ (Wm|Wv) [512,256] + bias.
// FFMA2 inner loop.
// ---------------------------------------------------------------------------
__global__ void __launch_bounds__(256) k_heads(
    const float* __restrict__ Wm, const float* __restrict__ bm,
    const float* __restrict__ Wv, const float* __restrict__ bv,
    float* __restrict__ out)
{
    const int n0 = blockIdx.x * 64;
    const int m0 = blockIdx.y * 128;
    const bool isV = (n0 >= 256);
    const float* W  = isV ? Wv : Wm;
    const float* bb = isV ? bv : bm;
    const int nw = n0 & 255;

    __shared__ __align__(16) float As[16][136];
    __shared__ __align__(16) ull   Bs2[16][64];

    const int tid = threadIdx.x;
    const int ti = tid >> 4, tj = tid & 15;

    ull acc2[4][4];
#pragma unroll
    for (int i = 0; i < 4; ++i)
#pragma unroll
        for (int j = 0; j < 4; ++j) acc2[i][j] = 0ull;

    for (int k0 = 0; k0 < 512; k0 += 16) {
#pragma unroll
        for (int p = 0; p < 8; ++p) {
            int idx = tid + p * 256;
            int r = idx >> 4, c = idx & 15;
            As[c][r] = g_outc[(size_t)(m0 + r) * 512 + k0 + c];
        }
#pragma unroll
        for (int p = 0; p < 4; ++p) {
            int idx = tid + p * 256;
            int r = idx >> 6, c = idx & 63;
            float bv2 = W[(size_t)(k0 + r) * 256 + nw + c];
            Bs2[r][c] = pack2(bv2, bv2);
        }
        __syncthreads();
#pragma unroll
        for (int kk = 0; kk < 16; ++kk) {
            ull ap[4];
            const ull* arow = (const ull*)&As[kk][ti * 8];
            ap[0] = arow[0]; ap[1] = arow[1]; ap[2] = arow[2]; ap[3] = arow[3];
            ull bd[4];
            const ull* brow = &Bs2[kk][tj * 4];
            bd[0] = brow[0]; bd[1] = brow[1]; bd[2] = brow[2]; bd[3] = brow[3];
#pragma unroll
            for (int i = 0; i < 4; ++i)
#pragma unroll
                for (int jj = 0; jj < 4; ++jj)
                    acc2[i][jj] = ffma2(ap[i], bd[jj], acc2[i][jj]);
        }
        __syncthreads();
    }

    const size_t hofs = (size_t)M_ * H_;
    float4 bb4 = *(const float4*)&bb[nw + tj * 4];
#pragma unroll
    for (int i = 0; i < 4; ++i) {
        float4 o0, o1;
        unpack2(acc2[i][0], o0.x, o1.x);
        unpack2(acc2[i][1], o0.y, o1.y);
        unpack2(acc2[i][2], o0.z, o1.z);
        unpack2(acc2[i][3], o0.w, o1.w);
        o0.x += bb4.x; o0.y += bb4.y; o0.z += bb4.z; o0.w += bb4.w;
        o1.x += bb4.x; o1.y += bb4.y; o1.z += bb4.z; o1.w += bb4.w;
        int r0 = m0 + ti * 8 + i * 2, r1 = r0 + 1;
        if (isV) {
            o0.x = expf(o0.x); o0.y = expf(o0.y); o0.z = expf(o0.z); o0.w = expf(o0.w);
            o1.x = expf(o1.x); o1.y = expf(o1.y); o1.z = expf(o1.z); o1.w = expf(o1.w);
            *(float4*)&out[(size_t)r0 * 256 + nw + tj * 4] = o0;
            *(float4*)&out[(size_t)r1 * 256 + nw + tj * 4] = o1;
        } else {
            *(float4*)&out[hofs + (size_t)r0 * 256 + nw + tj * 4] = o0;
            *(float4*)&out[hofs + (size_t)r1 * 256 + nw + tj * 4] = o1;
        }
    }
}

// ---------------------------------------------------------------------------
extern "C" void kernel_launch(void* const* d_in, const int* in_sizes, int n_in,
                              void* d_out, int out_size)
{
    const float* inputs = (const float*)d_in[0];
    const float* Wi_f   = (const float*)d_in[1];
    const float* bi_f   = (const float*)d_in[2];
    const float* Wh_f   = (const float*)d_in[3];
    const float* bhn_f  = (const float*)d_in[4];
    const float* Wi_b   = (const float*)d_in[5];
    const float* bi_b   = (const float*)d_in[6];
    const float* Wh_b   = (const float*)d_in[7];
    const float* bhn_b  = (const float*)d_in[8];
    const float* Wm     = (const float*)d_in[9];
    const float* bm     = (const float*)d_in[10];
    const float* Wv     = (const float*)d_in[11];
    const float* bv     = (const float*)d_in[12];
    float* out = (float*)d_out;

    (void)in_sizes; (void)n_in; (void)out_size;

    k_xgemm<<<dim3(12, 256, 2), 256>>>(inputs, Wi_f, bi_f, Wi_b, bi_b);
    k_scan<<<128, 256>>>(Wh_f, bhn_f, Wh_b, bhn_b);
    k_heads<<<dim3(8, 256), 256>>>(Wm, bm, Wv, bv, out);
}

// round 7
// speedup vs baseline: 1.4644x; 1.0233x over previous
#include <cuda_runtime.h>
#include <cstdint>

#define B_ 8
#define T_ 4096
#define D_ 256
#define H_ 256
#define G_ 768              // 3H
#define M_ (B_ * T_)        // 32768

// Scratch (static device allocations only)
// xg layout (scan-permuted): [d][b][t][rank(8)][w(8)][12]  (12 = gate*4 + j)
__device__ float g_xg[(size_t)2 * B_ * T_ * G_];
__device__ float g_outc[(size_t)B_ * T_ * 2 * H_];     // [b][t][512]  (fwd | bwd)

typedef unsigned long long ull;

__device__ __forceinline__ uint32_t s2u(const void* p) {
    uint32_t a;
    asm("{ .reg .u64 t; cvta.to.shared.u64 t, %1; cvt.u32.u64 %0, t; }"
        : "=r"(a) : "l"(p));
    return a;
}
__device__ __forceinline__ ull ffma2(ull a, ull b, ull c) {
    ull d;
    asm("fma.rn.f32x2 %0, %1, %2, %3;" : "=l"(d) : "l"(a), "l"(b), "l"(c));
    return d;
}
__device__ __forceinline__ ull fadd2(ull a, ull b) {
    ull d;
    asm("add.rn.f32x2 %0, %1, %2;" : "=l"(d) : "l"(a), "l"(b));
    return d;
}
__device__ __forceinline__ ull pack2(float lo, float hi) {
    ull r;
    asm("mov.b64 %0, {%1, %2};" : "=l"(r)
        : "r"(__float_as_uint(lo)), "r"(__float_as_uint(hi)));
    return r;
}
__device__ __forceinline__ void unpack2(ull a, float& lo, float& hi) {
    uint32_t l, h;
    asm("mov.b64 {%0, %1}, %2;" : "=r"(l), "=r"(h) : "l"(a));
    lo = __uint_as_float(l); hi = __uint_as_float(h);
}
__device__ __forceinline__ float sum2(ull a) {
    float lo, hi; unpack2(a, lo, hi); return lo + hi;
}
__device__ __forceinline__ unsigned ldacq_sh(uint32_t a) {
    unsigned v;
    asm volatile("ld.acquire.cluster.shared::cta.u32 %0, [%1];"
                 : "=r"(v) : "r"(a) : "memory");
    return v;
}

// ---------------------------------------------------------------------------
// Kernel A: xg[d] = X @ Wi_d + bi_d   X:[32768,256], Wi:[256,768]
// FFMA2 inner loop. Output permuted to scan layout.
// ---------------------------------------------------------------------------
__global__ void __launch_bounds__(256) k_xgemm(
    const float* __restrict__ X,
    const float* __restrict__ Wi_f, const float* __restrict__ bi_f,
    const float* __restrict__ Wi_b, const float* __restrict__ bi_b)
{
    const int d = blockIdx.z;
    const float* W  = d ? Wi_b : Wi_f;
    const float* bi = d ? bi_b : bi_f;
    float* out = g_xg + (size_t)d * M_ * G_;

    const int m0 = blockIdx.y * 128;
    const int n0 = blockIdx.x * 64;

    __shared__ __align__(16) float As[16][136];
    __shared__ __align__(16) ull   Bs2[16][64];

    const int tid = threadIdx.x;
    const int ti = tid >> 4;
    const int tj = tid & 15;

    ull acc2[4][4];
#pragma unroll
    for (int i = 0; i < 4; ++i)
#pragma unroll
        for (int j = 0; j < 4; ++j) acc2[i][j] = 0ull;

    for (int k0 = 0; k0 < D_; k0 += 16) {
#pragma unroll
        for (int p = 0; p < 8; ++p) {
            int idx = tid + p * 256;
            int r = idx >> 4, c = idx & 15;
            As[c][r] = X[(size_t)(m0 + r) * D_ + k0 + c];
        }
#pragma unroll
        for (int p = 0; p < 4; ++p) {
            int idx = tid + p * 256;
            int r = idx >> 6, c = idx & 63;
            float bv = W[(size_t)(k0 + r) * G_ + n0 + c];
            Bs2[r][c] = pack2(bv, bv);
        }
        __syncthreads();
#pragma unroll
        for (int kk = 0; kk < 16; ++kk) {
            ull ap[4];
            const ull* arow = (const ull*)&As[kk][ti * 8];
            ap[0] = arow[0]; ap[1] = arow[1]; ap[2] = arow[2]; ap[3] = arow[3];
            ull bd[4];
            const ull* brow = &Bs2[kk][tj * 4];
            bd[0] = brow[0]; bd[1] = brow[1]; bd[2] = brow[2]; bd[3] = brow[3];
#pragma unroll
            for (int i = 0; i < 4; ++i)
#pragma unroll
                for (int j = 0; j < 4; ++j)
                    acc2[i][j] = ffma2(ap[i], bd[j], acc2[i][j]);
        }
        __syncthreads();
    }

    const int n = n0 + tj * 4;
    const int g = n >> 8, u = n & 255;
    const int pos = (u >> 5) * 96 + ((u >> 2) & 7) * 12 + g * 4;
    float4 bb = *(const float4*)&bi[n];
#pragma unroll
    for (int i = 0; i < 4; ++i) {
        float4 o0, o1;
        unpack2(acc2[i][0], o0.x, o1.x);
        unpack2(acc2[i][1], o0.y, o1.y);
        unpack2(acc2[i][2], o0.z, o1.z);
        unpack2(acc2[i][3], o0.w, o1.w);
        o0.x += bb.x; o0.y += bb.y; o0.z += bb.z; o0.w += bb.w;
        o1.x += bb.x; o1.y += bb.y; o1.z += bb.z; o1.w += bb.w;
        *(float4*)&out[(size_t)(m0 + ti * 8 + i * 2)     * G_ + pos] = o0;
        *(float4*)&out[(size_t)(m0 + ti * 8 + i * 2 + 1) * G_ + pos] = o1;
    }
}

// ---------------------------------------------------------------------------
// Kernel B: clustered bidirectional GRU scan (16 clusters x 8 CTAs).
// COALESCED DSMEM exchange: each warp delivers the CTA's full 128B h-block
// to exactly one peer (+ 32B of per-lane release flags). One BAR per step.
// ---------------------------------------------------------------------------
__global__ void __launch_bounds__(256, 1) __cluster_dims__(8, 1, 1)
k_scan(const float* __restrict__ Wh_f, const float* __restrict__ bhn_f,
       const float* __restrict__ Wh_b, const float* __restrict__ bhn_b)
{
    __shared__ __align__(16) float hbuf[3][288];   // rank r block at [r*36, r*36+32)
    __shared__ __align__(16) unsigned flags[64];   // [producer_rank*8 + lane]
    __shared__ __align__(16) float hloc[32];       // this CTA's current h slice
    __shared__ __align__(16) float hist[16][32];   // output staging, double 8-block

    const uint32_t hbuf_a = s2u(hbuf);
    const uint32_t flag_a = s2u(flags);

    const int rank = blockIdx.x & 7;
    const int cid  = blockIdx.x >> 3;
    const int d    = cid >> 3;
    const int b    = cid & 7;

    const float* Wh  = d ? Wh_b  : Wh_f;
    const float* bhn = d ? bhn_b : bhn_f;

    const int tid  = threadIdx.x;
    const int w    = tid >> 5;
    const int lane = tid & 31;
    const int kq   = lane >> 2;
    const int j    = lane & 3;
    const int unit = rank * 32 + w * 4 + j;

    // W slice into packed f32x2 registers (48 x b64 per lane)
    ull Wr2[16], Wz2[16], Wn2[16];
#pragma unroll
    for (int kk = 0; kk < 16; ++kk) {
        size_t r0 = (size_t)(kq * 32 + kk * 2) * G_;
        size_t r1 = r0 + G_;
        Wr2[kk] = pack2(__ldg(Wh + r0 + unit),       __ldg(Wh + r1 + unit));
        Wz2[kk] = pack2(__ldg(Wh + r0 + 256 + unit), __ldg(Wh + r1 + 256 + unit));
        Wn2[kk] = pack2(__ldg(Wh + r0 + 512 + unit), __ldg(Wh + r1 + 512 + unit));
    }

    for (int i = tid; i < 3 * 288; i += 256) ((float*)hbuf)[i] = 0.f;  // h0 = 0
    if (tid < 64) flags[tid] = 0u;
    if (tid < 32) hloc[tid] = 0.f;
    __syncthreads();
    asm volatile("barrier.cluster.arrive.aligned;" ::: "memory");
    asm volatile("barrier.cluster.wait.aligned;"   ::: "memory");

    // warp w's delivery target: peer (rank + w) & 7  (rotation staggers receivers)
    const uint32_t peer = (uint32_t)((rank + w) & 7);
    uint32_t rhb, rfb;
    asm("mapa.shared::cluster.u32 %0, %1, %2;" : "=r"(rhb) : "r"(hbuf_a), "r"(peer));
    asm("mapa.shared::cluster.u32 %0, %1, %2;" : "=r"(rfb) : "r"(flag_a), "r"(peer));
    const uint32_t rdata = rhb + (uint32_t)(rank * 144 + lane * 16);  // +pn*1152
    const uint32_t rflag = rfb + (uint32_t)(rank * 8 + lane) * 4;

    // consumer poll addresses: 2 flags per lane
    const uint32_t fa0 = flag_a + (uint32_t)lane * 4;
    const uint32_t fa1 = flag_a + (uint32_t)(lane + 32) * 4;

    const float bhn_u = bhn[unit];
    const float* xgp = g_xg + ((size_t)(d * B_ + b)) * T_ * G_ + rank * 96 + w * 12;

    // 3-deep gi prefetch ring (lanes 0..11, contiguous 48B per warp)
    float gv0 = 0.f, gv1 = 0.f, gv2 = 0.f;
    if (lane < 12) {
        gv0 = __ldg(xgp + (size_t)(d ? T_ - 1 : 0) * G_ + lane);
        gv1 = __ldg(xgp + (size_t)(d ? T_ - 2 : 1) * G_ + lane);
        gv2 = __ldg(xgp + (size_t)(d ? T_ - 3 : 2) * G_ + lane);
    }

    float hprev = 0.f;     // every lane mirrors its unit j's h
    int p = 0;

    for (int s = 0; s < T_; ++s) {
        const unsigned us = (unsigned)s;

        // ---- wait: all 64 producer flags >= s ----
        for (;;) {
            unsigned f0 = ldacq_sh(fa0);
            unsigned f1 = ldacq_sh(fa1);
            if (__all_sync(0xFFFFFFFFu, (f0 >= us) && (f1 >= us))) break;
        }

        // ---- 3 packed dots over this lane's 32-K chunk ----
        const float* hp = &hbuf[p][kq * 36];
        ull ar0 = 0, ar1 = 0, az0 = 0, az1 = 0, an0 = 0, an1 = 0;
#pragma unroll
        for (int q = 0; q < 8; ++q) {
            ulonglong2 hv2 = *(const ulonglong2*)(hp + q * 4);
            ar0 = ffma2(Wr2[q * 2],     hv2.x, ar0);
            ar1 = ffma2(Wr2[q * 2 + 1], hv2.y, ar1);
            az0 = ffma2(Wz2[q * 2],     hv2.x, az0);
            az1 = ffma2(Wz2[q * 2 + 1], hv2.y, az1);
            an0 = ffma2(Wn2[q * 2],     hv2.x, an0);
            an1 = ffma2(Wn2[q * 2 + 1], hv2.y, an1);
        }
        float sr = sum2(fadd2(ar0, ar1));
        float sz = sum2(fadd2(az0, az1));
        float sn = sum2(fadd2(an0, an1));
#pragma unroll
        for (int m = 16; m >= 4; m >>= 1) {
            sr += __shfl_xor_sync(0xFFFFFFFFu, sr, m);
            sz += __shfl_xor_sync(0xFFFFFFFFu, sz, m);
            sn += __shfl_xor_sync(0xFFFFFFFFu, sn, m);
        }

        float gr = __shfl_sync(0xFFFFFFFFu, gv0, j);
        float gz = __shfl_sync(0xFFFFFFFFu, gv0, 4 + j);
        float gn = __shfl_sync(0xFFFFFFFFu, gv0, 8 + j);

        {
            float r = 1.f / (1.f + expf(-(gr + sr)));
            float z = 1.f / (1.f + expf(-(gz + sz)));
            float n = tanhf(fmaf(r, sn + bhn_u, gn));
            hprev = fmaf(z, hprev - n, n);           // h_new, all lanes
        }

        // stage h + output history (lanes 0..3 own units w*4+lane)
        if (lane < 4) {
            hloc[w * 4 + lane] = hprev;
            hist[s & 15][w * 4 + lane] = hprev;
        }
        __syncthreads();    // hloc/hist complete CTA-wide

        if (s + 1 < T_) {
            const int pn = (p + 1 == 3) ? 0 : p + 1;

            // ---- coalesced delivery: warp w -> peer (rank+w)&7 ----
            if (lane < 8) {
                float4 v = *(const float4*)&hloc[lane * 4];
                asm volatile("st.shared::cluster.v4.b32 [%0], {%1, %2, %3, %4};"
                             :: "r"(rdata + (uint32_t)pn * 1152),
                                "r"(__float_as_uint(v.x)), "r"(__float_as_uint(v.y)),
                                "r"(__float_as_uint(v.z)), "r"(__float_as_uint(v.w))
                             : "memory");
                asm volatile("st.release.cluster.shared::cluster.u32 [%0], %1;"
                             :: "r"(rflag), "r"((unsigned)(s + 1)) : "memory");
            }

            // advance gi ring (prefetch s+3)
            gv0 = gv1; gv1 = gv2;
            if (lane < 12 && s + 3 < T_) {
                const int tn = d ? (T_ - 4 - s) : (s + 3);
                gv2 = __ldg(xgp + (size_t)tn * G_ + lane);
            }
            p = pn;
        }

        // coalesced 8-step output flush (reads the half just completed)
        if ((s & 7) == 7) {
            const int s0 = s - 7 + w;
            const int tw = d ? (T_ - 1 - s0) : s0;
            g_outc[((size_t)b * T_ + tw) * 512 + d * 256 + rank * 32 + lane] =
                hist[s0 & 15][lane];
        }
    }
}

// ---------------------------------------------------------------------------
// Kernel C: heads. out_combined [32768,512] @ (Wm|Wv) [512,256] + bias. FFMA2.
// ---------------------------------------------------------------------------
__global__ void __launch_bounds__(256) k_heads(
    const float* __restrict__ Wm, const float* __restrict__ bm,
    const float* __restrict__ Wv, const float* __restrict__ bv,
    float* __restrict__ out)
{
    const int n0 = blockIdx.x * 64;
    const int m0 = blockIdx.y * 128;
    const bool isV = (n0 >= 256);
    const float* W  = isV ? Wv : Wm;
    const float* bb = isV ? bv : bm;
    const int nw = n0 & 255;

    __shared__ __align__(16) float As[16][136];
    __shared__ __align__(16) ull   Bs2[16][64];

    const int tid = threadIdx.x;
    const int ti = tid >> 4, tj = tid & 15;

    ull acc2[4][4];
#pragma unroll
    for (int i = 0; i < 4; ++i)
#pragma unroll
        for (int j = 0; j < 4; ++j) acc2[i][j] = 0ull;

    for (int k0 = 0; k0 < 512; k0 += 16) {
#pragma unroll
        for (int p = 0; p < 8; ++p) {
            int idx = tid + p * 256;
            int r = idx >> 4, c = idx & 15;
            As[c][r] = g_outc[(size_t)(m0 + r) * 512 + k0 + c];
        }
#pragma unroll
        for (int p = 0; p < 4; ++p) {
            int idx = tid + p * 256;
            int r = idx >> 6, c = idx & 63;
            float bv2 = W[(size_t)(k0 + r) * 256 + nw + c];
            Bs2[r][c] = pack2(bv2, bv2);
        }
        __syncthreads();
#pragma unroll
        for (int kk = 0; kk < 16; ++kk) {
            ull ap[4];
            const ull* arow = (const ull*)&As[kk][ti * 8];
            ap[0] = arow[0]; ap[1] = arow[1]; ap[2] = arow[2]; ap[3] = arow[3];
            ull bd[4];
            const ull* brow = &Bs2[kk][tj * 4];
            bd[0] = brow[0]; bd[1] = brow[1]; bd[2] = brow[2]; bd[3] = brow[3];
#pragma unroll
            for (int i = 0; i < 4; ++i)
#pragma unroll
                for (int jj = 0; jj < 4; ++jj)
                    acc2[i][jj] = ffma2(ap[i], bd[jj], acc2[i][jj]);
        }
        __syncthreads();
    }

    const size_t hofs = (size_t)M_ * H_;
    float4 bb4 = *(const float4*)&bb[nw + tj * 4];
#pragma unroll
    for (int i = 0; i < 4; ++i) {
        float4 o0, o1;
        unpack2(acc2[i][0], o0.x, o1.x);
        unpack2(acc2[i][1], o0.y, o1.y);
        unpack2(acc2[i][2], o0.z, o1.z);
        unpack2(acc2[i][3], o0.w, o1.w);
        o0.x += bb4.x; o0.y += bb4.y; o0.z += bb4.z; o0.w += bb4.w;
        o1.x += bb4.x; o1.y += bb4.y; o1.z += bb4.z; o1.w += bb4.w;
        int r0 = m0 + ti * 8 + i * 2, r1 = r0 + 1;
        if (isV) {
            o0.x = expf(o0.x); o0.y = expf(o0.y); o0.z = expf(o0.z); o0.w = expf(o0.w);
            o1.x = expf(o1.x); o1.y = expf(o1.y); o1.z = expf(o1.z); o1.w = expf(o1.w);
            *(float4*)&out[(size_t)r0 * 256 + nw + tj * 4] = o0;
            *(float4*)&out[(size_t)r1 * 256 + nw + tj * 4] = o1;
        } else {
            *(float4*)&out[hofs + (size_t)r0 * 256 + nw + tj * 4] = o0;
            *(float4*)&out[hofs + (size_t)r1 * 256 + nw + tj * 4] = o1;
        }
    }
}

// ---------------------------------------------------------------------------
extern "C" void kernel_launch(void* const* d_in, const int* in_sizes, int n_in,
                              void* d_out, int out_size)
{
    const float* inputs = (const float*)d_in[0];
    const float* Wi_f   = (const float*)d_in[1];
    const float* bi_f   = (const float*)d_in[2];
    const float* Wh_f   = (const float*)d_in[3];
    const float* bhn_f  = (const float*)d_in[4];
    const float* Wi_b   = (const float*)d_in[5];
    const float* bi_b   = (const float*)d_in[6];
    const float* Wh_b   = (const float*)d_in[7];
    const float* bhn_b  = (const float*)d_in[8];
    const float* Wm     = (const float*)d_in[9];
    const float* bm     = (const float*)d_in[10];
    const float* Wv     = (const float*)d_in[11];
    const float* bv     = (const float*)d_in[12];
    float* out = (float*)d_out;

    (void)in_sizes; (void)n_in; (void)out_size;

    k_xgemm<<<dim3(12, 256, 2), 256>>>(inputs, Wi_f, bi_f, Wi_b, bi_b);
    k_scan<<<128, 256>>>(Wh_f, bhn_f, Wh_b, bhn_b);
    k_heads<<<dim3(8, 256), 256>>>(Wm, bm, Wv, bv, out);
}

// round 8
// speedup vs baseline: 1.9875x; 1.3572x over previous
#include <cuda_runtime.h>
#include <cstdint>

#define B_ 8
#define T_ 4096
#define D_ 256
#define H_ 256
#define G_ 768              // 3H
#define M_ (B_ * T_)        // 32768
#define CANARY 0x7FC00001u  // NaN bit pattern; h is always finite

// Scratch (static device allocations only)
// xg layout (scan-permuted): [d][b][t][rank(8)][w(8)][12]  (12 = gate*4 + j)
__device__ float g_xg[(size_t)2 * B_ * T_ * G_];
__device__ float g_outc[(size_t)B_ * T_ * 2 * H_];     // [b][t][512]  (fwd | bwd)

typedef unsigned long long ull;

__device__ __forceinline__ uint32_t s2u(const void* p) {
    uint32_t a;
    asm("{ .reg .u64 t; cvta.to.shared.u64 t, %1; cvt.u32.u64 %0, t; }"
        : "=r"(a) : "l"(p));
    return a;
}
__device__ __forceinline__ ull ffma2(ull a, ull b, ull c) {
    ull d;
    asm("fma.rn.f32x2 %0, %1, %2, %3;" : "=l"(d) : "l"(a), "l"(b), "l"(c));
    return d;
}
__device__ __forceinline__ ull fadd2(ull a, ull b) {
    ull d;
    asm("add.rn.f32x2 %0, %1, %2;" : "=l"(d) : "l"(a), "l"(b));
    return d;
}
__device__ __forceinline__ ull pack2(float lo, float hi) {
    ull r;
    asm("mov.b64 %0, {%1, %2};" : "=l"(r)
        : "r"(__float_as_uint(lo)), "r"(__float_as_uint(hi)));
    return r;
}
__device__ __forceinline__ void unpack2(ull a, float& lo, float& hi) {
    uint32_t l, h;
    asm("mov.b64 {%0, %1}, %2;" : "=r"(l), "=r"(h) : "l"(a));
    lo = __uint_as_float(l); hi = __uint_as_float(h);
}
__device__ __forceinline__ float sum2(ull a) {
    float lo, hi; unpack2(a, lo, hi); return lo + hi;
}
__device__ __forceinline__ unsigned ldvol_sh(uint32_t a) {
    unsigned v;
    asm volatile("ld.volatile.shared.u32 %0, [%1];" : "=r"(v) : "r"(a) : "memory");
    return v;
}

// ---------------------------------------------------------------------------
// Kernel A: xg[d] = X @ Wi_d + bi_d   X:[32768,256], Wi:[256,768]
// FFMA2 inner loop. Output permuted to scan layout.
// ---------------------------------------------------------------------------
__global__ void __launch_bounds__(256) k_xgemm(
    const float* __restrict__ X,
    const float* __restrict__ Wi_f, const float* __restrict__ bi_f,
    const float* __restrict__ Wi_b, const float* __restrict__ bi_b)
{
    const int d = blockIdx.z;
    const float* W  = d ? Wi_b : Wi_f;
    const float* bi = d ? bi_b : bi_f;
    float* out = g_xg + (size_t)d * M_ * G_;

    const int m0 = blockIdx.y * 128;
    const int n0 = blockIdx.x * 64;

    __shared__ __align__(16) float As[16][136];
    __shared__ __align__(16) ull   Bs2[16][64];

    const int tid = threadIdx.x;
    const int ti = tid >> 4;
    const int tj = tid & 15;

    ull acc2[4][4];
#pragma unroll
    for (int i = 0; i < 4; ++i)
#pragma unroll
        for (int j = 0; j < 4; ++j) acc2[i][j] = 0ull;

    for (int k0 = 0; k0 < D_; k0 += 16) {
#pragma unroll
        for (int p = 0; p < 8; ++p) {
            int idx = tid + p * 256;
            int r = idx >> 4, c = idx & 15;
            As[c][r] = X[(size_t)(m0 + r) * D_ + k0 + c];
        }
#pragma unroll
        for (int p = 0; p < 4; ++p) {
            int idx = tid + p * 256;
            int r = idx >> 6, c = idx & 63;
            float bv = W[(size_t)(k0 + r) * G_ + n0 + c];
            Bs2[r][c] = pack2(bv, bv);
        }
        __syncthreads();
#pragma unroll
        for (int kk = 0; kk < 16; ++kk) {
            ull ap[4];
            const ull* arow = (const ull*)&As[kk][ti * 8];
            ap[0] = arow[0]; ap[1] = arow[1]; ap[2] = arow[2]; ap[3] = arow[3];
            ull bd[4];
            const ull* brow = &Bs2[kk][tj * 4];
            bd[0] = brow[0]; bd[1] = brow[1]; bd[2] = brow[2]; bd[3] = brow[3];
#pragma unroll
            for (int i = 0; i < 4; ++i)
#pragma unroll
                for (int j = 0; j < 4; ++j)
                    acc2[i][j] = ffma2(ap[i], bd[j], acc2[i][j]);
        }
        __syncthreads();
    }

    const int n = n0 + tj * 4;
    const int g = n >> 8, u = n & 255;
    const int pos = (u >> 5) * 96 + ((u >> 2) & 7) * 12 + g * 4;
    float4 bb = *(const float4*)&bi[n];
#pragma unroll
    for (int i = 0; i < 4; ++i) {
        float4 o0, o1;
        unpack2(acc2[i][0], o0.x, o1.x);
        unpack2(acc2[i][1], o0.y, o1.y);
        unpack2(acc2[i][2], o0.z, o1.z);
        unpack2(acc2[i][3], o0.w, o1.w);
        o0.x += bb.x; o0.y += bb.y; o0.z += bb.z; o0.w += bb.w;
        o1.x += bb.x; o1.y += bb.y; o1.z += bb.z; o1.w += bb.w;
        *(float4*)&out[(size_t)(m0 + ti * 8 + i * 2)     * G_ + pos] = o0;
        *(float4*)&out[(size_t)(m0 + ti * 8 + i * 2 + 1) * G_ + pos] = o1;
    }
}

// ---------------------------------------------------------------------------
// Kernel B: clustered bidirectional GRU scan (16 clusters x 8 CTAs).
// CANARY PROTOCOL: no flags, no release/acquire, no mbarriers. Producers
// issue weak st.shared::cluster.v4; consumers poll data words against a NaN
// canary with plain volatile LDS. Two __syncthreads per step.
// ---------------------------------------------------------------------------
__global__ void __launch_bounds__(256, 1) __cluster_dims__(8, 1, 1)
k_scan(const float* __restrict__ Wh_f, const float* __restrict__ bhn_f,
       const float* __restrict__ Wh_b, const float* __restrict__ bhn_b)
{
    __shared__ __align__(16) float hbuf[3][288];   // block r at [r*36, r*36+32)
    __shared__ __align__(16) float hloc[32];       // this CTA's current h slice
    __shared__ __align__(16) float hist[16][32];   // output staging

    const uint32_t hbuf_a = s2u(hbuf);

    const int rank = blockIdx.x & 7;
    const int cid  = blockIdx.x >> 3;
    const int d    = cid >> 3;
    const int b    = cid & 7;

    const float* Wh  = d ? Wh_b  : Wh_f;
    const float* bhn = d ? bhn_b : bhn_f;

    const int tid  = threadIdx.x;
    const int w    = tid >> 5;
    const int lane = tid & 31;
    const int kq   = lane >> 2;
    const int j    = lane & 3;
    const int unit = rank * 32 + w * 4 + j;

    // W slice into packed f32x2 registers (48 x b64 per lane)
    ull Wr2[16], Wz2[16], Wn2[16];
#pragma unroll
    for (int kk = 0; kk < 16; ++kk) {
        size_t r0 = (size_t)(kq * 32 + kk * 2) * G_;
        size_t r1 = r0 + G_;
        Wr2[kk] = pack2(__ldg(Wh + r0 + unit),       __ldg(Wh + r1 + unit));
        Wz2[kk] = pack2(__ldg(Wh + r0 + 256 + unit), __ldg(Wh + r1 + 256 + unit));
        Wn2[kk] = pack2(__ldg(Wh + r0 + 512 + unit), __ldg(Wh + r1 + 512 + unit));
    }

    // init: buf0 = h0 (zeros), buf1/buf2 = canary, hloc = 0
    for (int i = tid; i < 288; i += 256) {
        hbuf[0][i] = 0.f;
        ((unsigned*)hbuf[1])[i] = CANARY;
        ((unsigned*)hbuf[2])[i] = CANARY;
    }
    if (tid < 32) hloc[tid] = 0.f;
    __syncthreads();
    asm volatile("barrier.cluster.arrive.aligned;" ::: "memory");
    asm volatile("barrier.cluster.wait.aligned;"   ::: "memory");

    // warp w's delivery target: peer (rank + w) & 7
    const uint32_t peer = (uint32_t)((rank + w) & 7);
    uint32_t rhb;
    asm("mapa.shared::cluster.u32 %0, %1, %2;" : "=r"(rhb) : "r"(hbuf_a), "r"(peer));
    const uint32_t rdata = rhb + (uint32_t)(rank * 144 + lane * 16);   // + pn*1152

    // poll address: warp w watches producer-w's block, one word per lane
    const uint32_t pa = hbuf_a + (uint32_t)(w * 144 + lane * 4);       // + q*1152
    // re-canary address: same block layout
    // (hbuf[q2][w*36 + lane])

    const float bhn_u = bhn[unit];
    const float* xgp = g_xg + ((size_t)(d * B_ + b)) * T_ * G_ + rank * 96 + w * 12;

    // 3-deep gi prefetch ring
    float gv0 = 0.f, gv1 = 0.f, gv2 = 0.f;
    if (lane < 12) {
        gv0 = __ldg(xgp + (size_t)(d ? T_ - 1 : 0) * G_ + lane);
        gv1 = __ldg(xgp + (size_t)(d ? T_ - 2 : 1) * G_ + lane);
        gv2 = __ldg(xgp + (size_t)(d ? T_ - 3 : 2) * G_ + lane);
    }

    float hprev = 0.f;
    int q = 0;

    for (int s = 0; s < T_; ++s) {
        // ---- 1. poll: all 32 words of producer-w's block present ----
        {
            const uint32_t a = pa + (uint32_t)q * 1152;
            while (__any_sync(0xFFFFFFFFu, ldvol_sh(a) == CANARY)) { }
        }
        __syncthreads();   // all blocks confirmed; prior step fully done

        // ---- 2. dots over this lane's 32-K chunk ----
        const float* hp = &hbuf[q][kq * 36];
        ull ar0 = 0, ar1 = 0, az0 = 0, az1 = 0, an0 = 0, an1 = 0;
#pragma unroll
        for (int qq = 0; qq < 8; ++qq) {
            ulonglong2 hv2 = *(const ulonglong2*)(hp + qq * 4);
            ar0 = ffma2(Wr2[qq * 2],     hv2.x, ar0);
            ar1 = ffma2(Wr2[qq * 2 + 1], hv2.y, ar1);
            az0 = ffma2(Wz2[qq * 2],     hv2.x, az0);
            az1 = ffma2(Wz2[qq * 2 + 1], hv2.y, az1);
            an0 = ffma2(Wn2[qq * 2],     hv2.x, an0);
            an1 = ffma2(Wn2[qq * 2 + 1], hv2.y, an1);
        }
        float sr = sum2(fadd2(ar0, ar1));
        float sz = sum2(fadd2(az0, az1));
        float sn = sum2(fadd2(an0, an1));
#pragma unroll
        for (int m = 16; m >= 4; m >>= 1) {
            sr += __shfl_xor_sync(0xFFFFFFFFu, sr, m);
            sz += __shfl_xor_sync(0xFFFFFFFFu, sz, m);
            sn += __shfl_xor_sync(0xFFFFFFFFu, sn, m);
        }

        float gr = __shfl_sync(0xFFFFFFFFu, gv0, j);
        float gz = __shfl_sync(0xFFFFFFFFu, gv0, 4 + j);
        float gn = __shfl_sync(0xFFFFFFFFu, gv0, 8 + j);

        {
            float r = 1.f / (1.f + expf(-(gr + sr)));
            float z = 1.f / (1.f + expf(-(gz + sz)));
            float n = tanhf(fmaf(r, sn + bhn_u, gn));
            hprev = fmaf(z, hprev - n, n);           // h_new, all lanes
        }

        // ---- 3. stage h_new + hist; re-canary buffer (s+2)%3 ----
        if (lane < 4) {
            hloc[w * 4 + lane] = hprev;
            hist[s & 15][w * 4 + lane] = hprev;
        }
        {
            const int q2 = (q + 2 >= 3) ? q - 1 : q + 2;   // (s+2)%3
            ((unsigned*)hbuf[q2])[w * 36 + lane] = CANARY;
        }
        __syncthreads();   // drains staging + canary stores before sends

        // ---- 4. send: warp w delivers CTA's 32-unit block to one peer ----
        if (s + 1 < T_) {
            const int pn = (q + 1 == 3) ? 0 : q + 1;
            if (lane < 8) {
                float4 v = *(const float4*)&hloc[lane * 4];
                asm volatile("st.shared::cluster.v4.b32 [%0], {%1, %2, %3, %4};"
                             :: "r"(rdata + (uint32_t)pn * 1152),
                                "r"(__float_as_uint(v.x)), "r"(__float_as_uint(v.y)),
                                "r"(__float_as_uint(v.z)), "r"(__float_as_uint(v.w))
                             : "memory");
            }
            // advance gi ring (prefetch s+3)
            gv0 = gv1; gv1 = gv2;
            if (lane < 12 && s + 3 < T_) {
                const int tn = d ? (T_ - 4 - s) : (s + 3);
                gv2 = __ldg(xgp + (size_t)tn * G_ + lane);
            }
            q = pn;
        }

        // ---- 5. coalesced 8-step output flush ----
        if ((s & 7) == 7) {
            const int s0 = s - 7 + w;
            const int tw = d ? (T_ - 1 - s0) : s0;
            g_outc[((size_t)b * T_ + tw) * 512 + d * 256 + rank * 32 + lane] =
                hist[s0 & 15][lane];
        }
    }

    // no CTA may exit while peers can still write to its smem
    asm volatile("barrier.cluster.arrive.aligned;" ::: "memory");
    asm volatile("barrier.cluster.wait.aligned;"   ::: "memory");
}

// ---------------------------------------------------------------------------
// Kernel C: heads. out_combined [32768,512] @ (Wm|Wv) [512,256] + bias. FFMA2.
// ---------------------------------------------------------------------------
__global__ void __launch_bounds__(256) k_heads(
    const float* __restrict__ Wm, const float* __restrict__ bm,
    const float* __restrict__ Wv, const float* __restrict__ bv,
    float* __restrict__ out)
{
    const int n0 = blockIdx.x * 64;
    const int m0 = blockIdx.y * 128;
    const bool isV = (n0 >= 256);
    const float* W  = isV ? Wv : Wm;
    const float* bb = isV ? bv : bm;
    const int nw = n0 & 255;

    __shared__ __align__(16) float As[16][136];
    __shared__ __align__(16) ull   Bs2[16][64];

    const int tid = threadIdx.x;
    const int ti = tid >> 4, tj = tid & 15;

    ull acc2[4][4];
#pragma unroll
    for (int i = 0; i < 4; ++i)
#pragma unroll
        for (int j = 0; j < 4; ++j) acc2[i][j] = 0ull;

    for (int k0 = 0; k0 < 512; k0 += 16) {
#pragma unroll
        for (int p = 0; p < 8; ++p) {
            int idx = tid + p * 256;
            int r = idx >> 4, c = idx & 15;
            As[c][r] = g_outc[(size_t)(m0 + r) * 512 + k0 + c];
        }
#pragma unroll
        for (int p = 0; p < 4; ++p) {
            int idx = tid + p * 256;
            int r = idx >> 6, c = idx & 63;
            float bv2 = W[(size_t)(k0 + r) * 256 + nw + c];
            Bs2[r][c] = pack2(bv2, bv2);
        }
        __syncthreads();
#pragma unroll
        for (int kk = 0; kk < 16; ++kk) {
            ull ap[4];
            const ull* arow = (const ull*)&As[kk][ti * 8];
            ap[0] = arow[0]; ap[1] = arow[1]; ap[2] = arow[2]; ap[3] = arow[3];
            ull bd[4];
            const ull* brow = &Bs2[kk][tj * 4];
            bd[0] = brow[0]; bd[1] = brow[1]; bd[2] = brow[2]; bd[3] = brow[3];
#pragma unroll
            for (int i = 0; i < 4; ++i)
#pragma unroll
                for (int jj = 0; jj < 4; ++jj)
                    acc2[i][jj] = ffma2(ap[i], bd[jj], acc2[i][jj]);
        }
        __syncthreads();
    }

    const size_t hofs = (size_t)M_ * H_;
    float4 bb4 = *(const float4*)&bb[nw + tj * 4];
#pragma unroll
    for (int i = 0; i < 4; ++i) {
        float4 o0, o1;
        unpack2(acc2[i][0], o0.x, o1.x);
        unpack2(acc2[i][1], o0.y, o1.y);
        unpack2(acc2[i][2], o0.z, o1.z);
        unpack2(acc2[i][3], o0.w, o1.w);
        o0.x += bb4.x; o0.y += bb4.y; o0.z += bb4.z; o0.w += bb4.w;
        o1.x += bb4.x; o1.y += bb4.y; o1.z += bb4.z; o1.w += bb4.w;
        int r0 = m0 + ti * 8 + i * 2, r1 = r0 + 1;
        if (isV) {
            o0.x = expf(o0.x); o0.y = expf(o0.y); o0.z = expf(o0.z); o0.w = expf(o0.w);
            o1.x = expf(o1.x); o1.y = expf(o1.y); o1.z = expf(o1.z); o1.w = expf(o1.w);
            *(float4*)&out[(size_t)r0 * 256 + nw + tj * 4] = o0;
            *(float4*)&out[(size_t)r1 * 256 + nw + tj * 4] = o1;
        } else {
            *(float4*)&out[hofs + (size_t)r0 * 256 + nw + tj * 4] = o0;
            *(float4*)&out[hofs + (size_t)r1 * 256 + nw + tj * 4] = o1;
        }
    }
}

// ---------------------------------------------------------------------------
extern "C" void kernel_launch(void* const* d_in, const int* in_sizes, int n_in,
                              void* d_out, int out_size)
{
    const float* inputs = (const float*)d_in[0];
    const float* Wi_f   = (const float*)d_in[1];
    const float* bi_f   = (const float*)d_in[2];
    const float* Wh_f   = (const float*)d_in[3];
    const float* bhn_f  = (const float*)d_in[4];
    const float* Wi_b   = (const float*)d_in[5];
    const float* bi_b   = (const float*)d_in[6];
    const float* Wh_b   = (const float*)d_in[7];
    const float* bhn_b  = (const float*)d_in[8];
    const float* Wm     = (const float*)d_in[9];
    const float* bm     = (const float*)d_in[10];
    const float* Wv     = (const float*)d_in[11];
    const float* bv     = (const float*)d_in[12];
    float* out = (float*)d_out;

    (void)in_sizes; (void)n_in; (void)out_size;

    k_xgemm<<<dim3(12, 256, 2), 256>>>(inputs, Wi_f, bi_f, Wi_b, bi_b);
    k_scan<<<128, 256>>>(Wh_f, bhn_f, Wh_b, bhn_b);
    k_heads<<<dim3(8, 256), 256>>>(Wm, bm, Wv, bv, out);
}

// round 9
// speedup vs baseline: 2.9376x; 1.4780x over previous
#include <cuda_runtime.h>
#include <cstdint>

#define B_ 8
#define T_ 4096
#define D_ 256
#define H_ 256
#define G_ 768              // 3H
#define M_ (B_ * T_)        // 32768
#define CANARY 0x7FC00001u  // NaN pattern; h is always finite

// Scratch (static device allocations only)
// xg layout (scan-permuted): [d][b][t][rank(4)][w(8)][gate(3)][j(8)]
__device__ float g_xg[(size_t)2 * B_ * T_ * G_];
__device__ float g_outc[(size_t)B_ * T_ * 2 * H_];     // [b][t][512]  (fwd | bwd)

typedef unsigned long long ull;

__device__ __forceinline__ uint32_t s2u(const void* p) {
    uint32_t a;
    asm("{ .reg .u64 t; cvta.to.shared.u64 t, %1; cvt.u32.u64 %0, t; }"
        : "=r"(a) : "l"(p));
    return a;
}
__device__ __forceinline__ ull ffma2(ull a, ull b, ull c) {
    ull d;
    asm("fma.rn.f32x2 %0, %1, %2, %3;" : "=l"(d) : "l"(a), "l"(b), "l"(c));
    return d;
}
__device__ __forceinline__ ull fadd2(ull a, ull b) {
    ull d;
    asm("add.rn.f32x2 %0, %1, %2;" : "=l"(d) : "l"(a), "l"(b));
    return d;
}
__device__ __forceinline__ ull pack2(float lo, float hi) {
    ull r;
    asm("mov.b64 %0, {%1, %2};" : "=l"(r)
        : "r"(__float_as_uint(lo)), "r"(__float_as_uint(hi)));
    return r;
}
__device__ __forceinline__ void unpack2(ull a, float& lo, float& hi) {
    uint32_t l, h;
    asm("mov.b64 {%0, %1}, %2;" : "=r"(l), "=r"(h) : "l"(a));
    lo = __uint_as_float(l); hi = __uint_as_float(h);
}
__device__ __forceinline__ float sum2(ull a) {
    float lo, hi; unpack2(a, lo, hi); return lo + hi;
}
__device__ __forceinline__ float fast_sigmoid(float x) {
    float e, r;
    asm("ex2.approx.f32 %0, %1;" : "=f"(e) : "f"(-1.4426950408889634f * x));
    asm("rcp.approx.f32 %0, %1;" : "=f"(r) : "f"(1.0f + e));
    return r;
}
__device__ __forceinline__ float fast_tanh(float x) {
    float e, r;
    asm("ex2.approx.f32 %0, %1;" : "=f"(e) : "f"(-2.8853900817779268f * x));
    asm("rcp.approx.f32 %0, %1;" : "=f"(r) : "f"(1.0f + e));
    return fmaf(2.0f, r, -1.0f);
}

// ---------------------------------------------------------------------------
// Kernel A: xg[d] = X @ Wi_d + bi_d   X:[32768,256], Wi:[256,768]
// FFMA2 inner loop. Output permuted: col n -> rank*192 + w*24 + gate*8 + j.
// ---------------------------------------------------------------------------
__global__ void __launch_bounds__(256) k_xgemm(
    const float* __restrict__ X,
    const float* __restrict__ Wi_f, const float* __restrict__ bi_f,
    const float* __restrict__ Wi_b, const float* __restrict__ bi_b)
{
    const int d = blockIdx.z;
    const float* W  = d ? Wi_b : Wi_f;
    const float* bi = d ? bi_b : bi_f;
    float* out = g_xg + (size_t)d * M_ * G_;

    const int m0 = blockIdx.y * 128;
    const int n0 = blockIdx.x * 64;

    __shared__ __align__(16) float As[16][136];
    __shared__ __align__(16) ull   Bs2[16][64];

    const int tid = threadIdx.x;
    const int ti = tid >> 4;
    const int tj = tid & 15;

    ull acc2[4][4];
#pragma unroll
    for (int i = 0; i < 4; ++i)
#pragma unroll
        for (int j = 0; j < 4; ++j) acc2[i][j] = 0ull;

    for (int k0 = 0; k0 < D_; k0 += 16) {
#pragma unroll
        for (int p = 0; p < 8; ++p) {
            int idx = tid + p * 256;
            int r = idx >> 4, c = idx & 15;
            As[c][r] = X[(size_t)(m0 + r) * D_ + k0 + c];
        }
#pragma unroll
        for (int p = 0; p < 4; ++p) {
            int idx = tid + p * 256;
            int r = idx >> 6, c = idx & 63;
            float bv = W[(size_t)(k0 + r) * G_ + n0 + c];
            Bs2[r][c] = pack2(bv, bv);
        }
        __syncthreads();
#pragma unroll
        for (int kk = 0; kk < 16; ++kk) {
            ull ap[4];
            const ull* arow = (const ull*)&As[kk][ti * 8];
            ap[0] = arow[0]; ap[1] = arow[1]; ap[2] = arow[2]; ap[3] = arow[3];
            ull bd[4];
            const ull* brow = &Bs2[kk][tj * 4];
            bd[0] = brow[0]; bd[1] = brow[1]; bd[2] = brow[2]; bd[3] = brow[3];
#pragma unroll
            for (int i = 0; i < 4; ++i)
#pragma unroll
                for (int j = 0; j < 4; ++j)
                    acc2[i][j] = ffma2(ap[i], bd[j], acc2[i][j]);
        }
        __syncthreads();
    }

    // permuted store: n -> rank*192 + w*24 + gate*8 + j
    const int n = n0 + tj * 4;
    const int g = n >> 8, u = n & 255;
    const int pos = (u >> 6) * 192 + ((u >> 3) & 7) * 24 + g * 8 + (u & 7);
    float4 bb = *(const float4*)&bi[n];
#pragma unroll
    for (int i = 0; i < 4; ++i) {
        float4 o0, o1;
        unpack2(acc2[i][0], o0.x, o1.x);
        unpack2(acc2[i][1], o0.y, o1.y);
        unpack2(acc2[i][2], o0.z, o1.z);
        unpack2(acc2[i][3], o0.w, o1.w);
        o0.x += bb.x; o0.y += bb.y; o0.z += bb.z; o0.w += bb.w;
        o1.x += bb.x; o1.y += bb.y; o1.z += bb.z; o1.w += bb.w;
        *(float4*)&out[(size_t)(m0 + ti * 8 + i * 2)     * G_ + pos] = o0;
        *(float4*)&out[(size_t)(m0 + ti * 8 + i * 2 + 1) * G_ + pos] = o1;
    }
}

// ---------------------------------------------------------------------------
// Kernel B: 4-CTA clustered bidirectional GRU scan (16 clusters x 4 CTAs).
// CTA = (dir, batch, 64-unit slice). W fully in registers (96 b64/thread).
// Canary protocol, per-warp full poll, ONE __syncthreads per step.
// ---------------------------------------------------------------------------
__global__ void __launch_bounds__(256, 1) __cluster_dims__(4, 1, 1)
k_scan(const float* __restrict__ Wh_f, const float* __restrict__ bhn_f,
       const float* __restrict__ Wh_b, const float* __restrict__ bhn_b)
{
    __shared__ __align__(16) float hbuf[3][272];   // 4 blocks x (64 data + 4 pad)
    __shared__ __align__(16) float hloc[2][64];    // double-buffered staged h
    __shared__ __align__(16) float hist[16][64];   // output staging

    const uint32_t hbuf_a = s2u(hbuf);

    const int rank = blockIdx.x & 3;
    const int cid  = blockIdx.x >> 2;
    const int d    = cid >> 3;
    const int b    = cid & 7;

    const float* Wh  = d ? Wh_b  : Wh_f;
    const float* bhn = d ? bhn_b : bhn_f;

    const int tid  = threadIdx.x;
    const int w    = tid >> 5;
    const int lane = tid & 31;
    const int kq   = lane >> 3;                    // K-chunk of 64 (0..3)
    const int j    = lane & 7;                     // unit within warp (0..7)
    const int unit = rank * 64 + w * 8 + j;

    // ---- W slice fully in registers: 96 b64 per lane ----
    ull Wr2[32], Wz2[32], Wn2[32];
#pragma unroll
    for (int kk = 0; kk < 32; ++kk) {
        size_t r0 = (size_t)(kq * 64 + kk * 2) * G_;
        size_t r1 = r0 + G_;
        Wr2[kk] = pack2(__ldg(Wh + r0 + unit),       __ldg(Wh + r1 + unit));
        Wz2[kk] = pack2(__ldg(Wh + r0 + 256 + unit), __ldg(Wh + r1 + 256 + unit));
        Wn2[kk] = pack2(__ldg(Wh + r0 + 512 + unit), __ldg(Wh + r1 + 512 + unit));
    }

    // init: buf0 = h0 = 0, buf1/buf2 = canary
    for (int i = tid; i < 272; i += 256) {
        hbuf[0][i] = 0.f;
        ((unsigned*)hbuf[1])[i] = CANARY;
        ((unsigned*)hbuf[2])[i] = CANARY;
    }
    if (tid < 128) ((float*)hloc)[tid] = 0.f;
    __syncthreads();
    asm volatile("barrier.cluster.arrive.aligned;" ::: "memory");
    asm volatile("barrier.cluster.wait.aligned;"   ::: "memory");

    // remote address for warps 1..3 (peer = (rank + w) & 3)
    uint32_t rdata = 0;
    if (w >= 1 && w <= 3) {
        uint32_t peer = (uint32_t)((rank + w) & 3);
        uint32_t rhb;
        asm("mapa.shared::cluster.u32 %0, %1, %2;" : "=r"(rhb) : "r"(hbuf_a), "r"(peer));
        rdata = rhb + (uint32_t)(rank * 272 + lane * 16);   // + pn*1088 (bytes)
    }

    // poll: lane covers block (lane>>3), words (lane&7)*8 .. +8  (2 x v4)
    const uint32_t pa = hbuf_a + (uint32_t)(kq * 272 + j * 32);

    const float bhn_u = bhn[unit];
    const float* xgp = g_xg + ((size_t)(d * B_ + b)) * T_ * G_ + rank * 192 + w * 24;

    // 3-deep gi prefetch ring (lanes 0..23: gate = lane>>3, j = lane&7)
    float gv0 = 0.f, gv1 = 0.f, gv2 = 0.f;
    if (lane < 24) {
        gv0 = __ldg(xgp + (size_t)(d ? T_ - 1 : 0) * G_ + lane);
        gv1 = __ldg(xgp + (size_t)(d ? T_ - 2 : 1) * G_ + lane);
        gv2 = __ldg(xgp + (size_t)(d ? T_ - 3 : 2) * G_ + lane);
    }

    float hprev = 0.f;
    int q = 0;

    for (int s = 0; s < T_; ++s) {
        // ---- 1. per-warp full poll: all 256 h words present ----
        {
            const uint32_t a = pa + (uint32_t)q * 1088;
            for (;;) {
                uint32_t x0, x1, x2, x3, y0, y1, y2, y3;
                asm volatile("ld.volatile.shared.v4.u32 {%0,%1,%2,%3}, [%4];"
                             : "=r"(x0), "=r"(x1), "=r"(x2), "=r"(x3) : "r"(a));
                asm volatile("ld.volatile.shared.v4.u32 {%0,%1,%2,%3}, [%4];"
                             : "=r"(y0), "=r"(y1), "=r"(y2), "=r"(y3) : "r"(a + 16));
                bool bad = (x0 == CANARY) | (x1 == CANARY) | (x2 == CANARY) |
                           (x3 == CANARY) | (y0 == CANARY) | (y1 == CANARY) |
                           (y2 == CANARY) | (y3 == CANARY);
                if (!__any_sync(0xFFFFFFFFu, bad)) break;
            }
        }

        // ---- 2. dots: this lane's 64-K chunk (block kq) ----
        const float* hp = &hbuf[q][kq * 68];
        ull ar0 = 0, ar1 = 0, az0 = 0, az1 = 0, an0 = 0, an1 = 0;
#pragma unroll
        for (int qq = 0; qq < 16; ++qq) {
            ulonglong2 hv2 = *(const ulonglong2*)(hp + qq * 4);
            ar0 = ffma2(Wr2[qq * 2],     hv2.x, ar0);
            ar1 = ffma2(Wr2[qq * 2 + 1], hv2.y, ar1);
            az0 = ffma2(Wz2[qq * 2],     hv2.x, az0);
            az1 = ffma2(Wz2[qq * 2 + 1], hv2.y, az1);
            an0 = ffma2(Wn2[qq * 2],     hv2.x, an0);
            an1 = ffma2(Wn2[qq * 2 + 1], hv2.y, an1);
        }
        float sr = sum2(fadd2(ar0, ar1));
        float sz = sum2(fadd2(az0, az1));
        float sn = sum2(fadd2(an0, an1));
#pragma unroll
        for (int m = 8; m <= 16; m <<= 1) {        // reduce over kq: xor 8, 16
            sr += __shfl_xor_sync(0xFFFFFFFFu, sr, m);
            sz += __shfl_xor_sync(0xFFFFFFFFu, sz, m);
            sn += __shfl_xor_sync(0xFFFFFFFFu, sn, m);
        }

        float gr = __shfl_sync(0xFFFFFFFFu, gv0, j);
        float gz = __shfl_sync(0xFFFFFFFFu, gv0, 8 + j);
        float gn = __shfl_sync(0xFFFFFFFFu, gv0, 16 + j);

        {
            float r = fast_sigmoid(gr + sr);
            float z = fast_sigmoid(gz + sz);
            float n = fast_tanh(fmaf(r, sn + bhn_u, gn));
            hprev = fmaf(z, hprev - n, n);          // h_new, all lanes
        }

        // ---- 3. stage (double-buffered) + hist; re-canary buf (s+2)%3 ----
        if (kq == 0) {
            hloc[s & 1][w * 8 + j] = hprev;
            hist[s & 15][w * 8 + j] = hprev;
        }
        {
            const int q2 = (q + 2 >= 3) ? q - 1 : q + 2;
            ((unsigned*)hbuf[q2])[(tid >> 6) * 68 + (tid & 63)] = CANARY;
        }
        __syncthreads();   // the ONE barrier: drains stage + canaries

        // ---- 4. send ----
        if (s + 1 < T_) {
            const int pn = (q + 1 == 3) ? 0 : q + 1;
            if (w == 0) {
                if (lane < 16)
                    *(float4*)&hbuf[pn][rank * 68 + lane * 4] =
                        *(const float4*)&hloc[s & 1][lane * 4];
            } else if (w <= 3) {
                if (lane < 16) {
                    float4 v = *(const float4*)&hloc[s & 1][lane * 4];
                    asm volatile("st.shared::cluster.v4.b32 [%0], {%1, %2, %3, %4};"
                                 :: "r"(rdata + (uint32_t)pn * 1088),
                                    "r"(__float_as_uint(v.x)), "r"(__float_as_uint(v.y)),
                                    "r"(__float_as_uint(v.z)), "r"(__float_as_uint(v.w))
                                 : "memory");
                }
            }
            // advance gi ring (prefetch s+3)
            gv0 = gv1; gv1 = gv2;
            if (lane < 24 && s + 3 < T_) {
                const int tn = d ? (T_ - 4 - s) : (s + 3);
                gv2 = __ldg(xgp + (size_t)tn * G_ + lane);
            }
            q = pn;
        }

        // ---- 5. coalesced 8-step output flush ----
        if ((s & 7) == 7) {
            const int s0 = s - 7 + w;
            const int tw = d ? (T_ - 1 - s0) : s0;
            *(float2*)&g_outc[((size_t)b * T_ + tw) * 512 + d * 256 + rank * 64 + lane * 2] =
                *(const float2*)&hist[s0 & 15][lane * 2];
        }
    }

    // no CTA may exit while peers can still write its smem
    asm volatile("barrier.cluster.arrive.aligned;" ::: "memory");
    asm volatile("barrier.cluster.wait.aligned;"   ::: "memory");
}

// ---------------------------------------------------------------------------
// Kernel C: heads. out_combined [32768,512] @ (Wm|Wv) [512,256] + bias. FFMA2.
// ---------------------------------------------------------------------------
__global__ void __launch_bounds__(256) k_heads(
    const float* __restrict__ Wm, const float* __restrict__ bm,
    const float* __restrict__ Wv, const float* __restrict__ bv,
    float* __restrict__ out)
{
    const int n0 = blockIdx.x * 64;
    const int m0 = blockIdx.y * 128;
    const bool isV = (n0 >= 256);
    const float* W  = isV ? Wv : Wm;
    const float* bb = isV ? bv : bm;
    const int nw = n0 & 255;

    __shared__ __align__(16) float As[16][136];
    __shared__ __align__(16) ull   Bs2[16][64];

    const int tid = threadIdx.x;
    const int ti = tid >> 4, tj = tid & 15;

    ull acc2[4][4];
#pragma unroll
    for (int i = 0; i < 4; ++i)
#pragma unroll
        for (int j = 0; j < 4; ++j) acc2[i][j] = 0ull;

    for (int k0 = 0; k0 < 512; k0 += 16) {
#pragma unroll
        for (int p = 0; p < 8; ++p) {
            int idx = tid + p * 256;
            int r = idx >> 4, c = idx & 15;
            As[c][r] = g_outc[(size_t)(m0 + r) * 512 + k0 + c];
        }
#pragma unroll
        for (int p = 0; p < 4; ++p) {
            int idx = tid + p * 256;
            int r = idx >> 6, c = idx & 63;
            float bv2 = W[(size_t)(k0 + r) * 256 + nw + c];
            Bs2[r][c] = pack2(bv2, bv2);
        }
        __syncthreads();
#pragma unroll
        for (int kk = 0; kk < 16; ++kk) {
            ull ap[4];
            const ull* arow = (const ull*)&As[kk][ti * 8];
            ap[0] = arow[0]; ap[1] = arow[1]; ap[2] = arow[2]; ap[3] = arow[3];
            ull bd[4];
            const ull* brow = &Bs2[kk][tj * 4];
            bd[0] = brow[0]; bd[1] = brow[1]; bd[2] = brow[2]; bd[3] = brow[3];
#pragma unroll
            for (int i = 0; i < 4; ++i)
#pragma unroll
                for (int jj = 0; jj < 4; ++jj)
                    acc2[i][jj] = ffma2(ap[i], bd[jj], acc2[i][jj]);
        }
        __syncthreads();
    }

    const size_t hofs = (size_t)M_ * H_;
    float4 bb4 = *(const float4*)&bb[nw + tj * 4];
#pragma unroll
    for (int i = 0; i < 4; ++i) {
        float4 o0, o1;
        unpack2(acc2[i][0], o0.x, o1.x);
        unpack2(acc2[i][1], o0.y, o1.y);
        unpack2(acc2[i][2], o0.z, o1.z);
        unpack2(acc2[i][3], o0.w, o1.w);
        o0.x += bb4.x; o0.y += bb4.y; o0.z += bb4.z; o0.w += bb4.w;
        o1.x += bb4.x; o1.y += bb4.y; o1.z += bb4.z; o1.w += bb4.w;
        int r0 = m0 + ti * 8 + i * 2, r1 = r0 + 1;
        if (isV) {
            o0.x = expf(o0.x); o0.y = expf(o0.y); o0.z = expf(o0.z); o0.w = expf(o0.w);
            o1.x = expf(o1.x); o1.y = expf(o1.y); o1.z = expf(o1.z); o1.w = expf(o1.w);
            *(float4*)&out[(size_t)r0 * 256 + nw + tj * 4] = o0;
            *(float4*)&out[(size_t)r1 * 256 + nw + tj * 4] = o1;
        } else {
            *(float4*)&out[hofs + (size_t)r0 * 256 + nw + tj * 4] = o0;
            *(float4*)&out[hofs + (size_t)r1 * 256 + nw + tj * 4] = o1;
        }
    }
}

// ---------------------------------------------------------------------------
extern "C" void kernel_launch(void* const* d_in, const int* in_sizes, int n_in,
                              void* d_out, int out_size)
{
    const float* inputs = (const float*)d_in[0];
    const float* Wi_f   = (const float*)d_in[1];
    const float* bi_f   = (const float*)d_in[2];
    const float* Wh_f   = (const float*)d_in[3];
    const float* bhn_f  = (const float*)d_in[4];
    const float* Wi_b   = (const float*)d_in[5];
    const float* bi_b   = (const float*)d_in[6];
    const float* Wh_b   = (const float*)d_in[7];
    const float* bhn_b  = (const float*)d_in[8];
    const float* Wm     = (const float*)d_in[9];
    const float* bm     = (const float*)d_in[10];
    const float* Wv     = (const float*)d_in[11];
    const float* bv     = (const float*)d_in[12];
    float* out = (float*)d_out;

    (void)in_sizes; (void)n_in; (void)out_size;

    k_xgemm<<<dim3(12, 256, 2), 256>>>(inputs, Wi_f, bi_f, Wi_b, bi_b);
    k_scan<<<64, 256>>>(Wh_f, bhn_f, Wh_b, bhn_b);
    k_heads<<<dim3(8, 256), 256>>>(Wm, bm, Wv, bv, out);
}

// round 10
// speedup vs baseline: 3.1372x; 1.0680x over previous
#include <cuda_runtime.h>
#include <cstdint>

#define B_ 8
#define T_ 4096
#define D_ 256
#define H_ 256
#define G_ 768              // 3H
#define M_ (B_ * T_)        // 32768
#define CANARY 0x7FC00001u  // NaN pattern; h is always finite

// Scratch (static device allocations only)
// xg layout (scan-permuted): [d][b][t][rank(4)][w(8)][gate(3)][j(8)]
__device__ float g_xg[(size_t)2 * B_ * T_ * G_];
__device__ float g_outc[(size_t)B_ * T_ * 2 * H_];     // [b][t][512]  (fwd | bwd)

typedef unsigned long long ull;

__device__ __forceinline__ uint32_t s2u(const void* p) {
    uint32_t a;
    asm("{ .reg .u64 t; cvta.to.shared.u64 t, %1; cvt.u32.u64 %0, t; }"
        : "=r"(a) : "l"(p));
    return a;
}
__device__ __forceinline__ ull ffma2(ull a, ull b, ull c) {
    ull d;
    asm("fma.rn.f32x2 %0, %1, %2, %3;" : "=l"(d) : "l"(a), "l"(b), "l"(c));
    return d;
}
__device__ __forceinline__ ull fadd2(ull a, ull b) {
    ull d;
    asm("add.rn.f32x2 %0, %1, %2;" : "=l"(d) : "l"(a), "l"(b));
    return d;
}
__device__ __forceinline__ ull pack2(float lo, float hi) {
    ull r;
    asm("mov.b64 %0, {%1, %2};" : "=l"(r)
        : "r"(__float_as_uint(lo)), "r"(__float_as_uint(hi)));
    return r;
}
__device__ __forceinline__ void unpack2(ull a, float& lo, float& hi) {
    uint32_t l, h;
    asm("mov.b64 {%0, %1}, %2;" : "=r"(l), "=r"(h) : "l"(a));
    lo = __uint_as_float(l); hi = __uint_as_float(h);
}
__device__ __forceinline__ float sum2(ull a) {
    float lo, hi; unpack2(a, lo, hi); return lo + hi;
}
__device__ __forceinline__ float fast_sigmoid(float x) {
    float e, r;
    asm("ex2.approx.f32 %0, %1;" : "=f"(e) : "f"(-1.4426950408889634f * x));
    asm("rcp.approx.f32 %0, %1;" : "=f"(r) : "f"(1.0f + e));
    return r;
}
__device__ __forceinline__ float fast_tanh(float x) {
    float e, r;
    asm("ex2.approx.f32 %0, %1;" : "=f"(e) : "f"(-2.8853900817779268f * x));
    asm("rcp.approx.f32 %0, %1;" : "=f"(r) : "f"(1.0f + e));
    return fmaf(2.0f, r, -1.0f);
}

// ---------------------------------------------------------------------------
// Kernel A: xg[d] = X @ Wi_d + bi_d   X:[32768,256], Wi:[256,768]
// FFMA2 inner loop. Output permuted: col n -> rank*192 + w*24 + gate*8 + j.
// ---------------------------------------------------------------------------
__global__ void __launch_bounds__(256) k_xgemm(
    const float* __restrict__ X,
    const float* __restrict__ Wi_f, const float* __restrict__ bi_f,
    const float* __restrict__ Wi_b, const float* __restrict__ bi_b)
{
    const int d = blockIdx.z;
    const float* W  = d ? Wi_b : Wi_f;
    const float* bi = d ? bi_b : bi_f;
    float* out = g_xg + (size_t)d * M_ * G_;

    const int m0 = blockIdx.y * 128;
    const int n0 = blockIdx.x * 64;

    __shared__ __align__(16) float As[16][136];
    __shared__ __align__(16) ull   Bs2[16][64];

    const int tid = threadIdx.x;
    const int ti = tid >> 4;
    const int tj = tid & 15;

    ull acc2[4][4];
#pragma unroll
    for (int i = 0; i < 4; ++i)
#pragma unroll
        for (int j = 0; j < 4; ++j) acc2[i][j] = 0ull;

    for (int k0 = 0; k0 < D_; k0 += 16) {
#pragma unroll
        for (int p = 0; p < 8; ++p) {
            int idx = tid + p * 256;
            int r = idx >> 4, c = idx & 15;
            As[c][r] = X[(size_t)(m0 + r) * D_ + k0 + c];
        }
#pragma unroll
        for (int p = 0; p < 4; ++p) {
            int idx = tid + p * 256;
            int r = idx >> 6, c = idx & 63;
            float bv = W[(size_t)(k0 + r) * G_ + n0 + c];
            Bs2[r][c] = pack2(bv, bv);
        }
        __syncthreads();
#pragma unroll
        for (int kk = 0; kk < 16; ++kk) {
            ull ap[4];
            const ull* arow = (const ull*)&As[kk][ti * 8];
            ap[0] = arow[0]; ap[1] = arow[1]; ap[2] = arow[2]; ap[3] = arow[3];
            ull bd[4];
            const ull* brow = &Bs2[kk][tj * 4];
            bd[0] = brow[0]; bd[1] = brow[1]; bd[2] = brow[2]; bd[3] = brow[3];
#pragma unroll
            for (int i = 0; i < 4; ++i)
#pragma unroll
                for (int j = 0; j < 4; ++j)
                    acc2[i][j] = ffma2(ap[i], bd[j], acc2[i][j]);
        }
        __syncthreads();
    }

    // permuted store: n -> rank*192 + w*24 + gate*8 + j
    const int n = n0 + tj * 4;
    const int g = n >> 8, u = n & 255;
    const int pos = (u >> 6) * 192 + ((u >> 3) & 7) * 24 + g * 8 + (u & 7);
    float4 bb = *(const float4*)&bi[n];
#pragma unroll
    for (int i = 0; i < 4; ++i) {
        float4 o0, o1;
        unpack2(acc2[i][0], o0.x, o1.x);
        unpack2(acc2[i][1], o0.y, o1.y);
        unpack2(acc2[i][2], o0.z, o1.z);
        unpack2(acc2[i][3], o0.w, o1.w);
        o0.x += bb.x; o0.y += bb.y; o0.z += bb.z; o0.w += bb.w;
        o1.x += bb.x; o1.y += bb.y; o1.z += bb.z; o1.w += bb.w;
        *(float4*)&out[(size_t)(m0 + ti * 8 + i * 2)     * G_ + pos] = o0;
        *(float4*)&out[(size_t)(m0 + ti * 8 + i * 2 + 1) * G_ + pos] = o1;
    }
}

// ---------------------------------------------------------------------------
// Kernel B: 4-CTA clustered bidirectional GRU scan. FULLY WARP-AUTONOMOUS:
// 4-buffer canary ring, no __syncthreads in the loop, per-warp direct sends
// (each warp pushes its 8 units to all 4 CTAs incl. itself).
// ---------------------------------------------------------------------------
__global__ void __launch_bounds__(256, 1) __cluster_dims__(4, 1, 1)
k_scan(const float* __restrict__ Wh_f, const float* __restrict__ bhn_f,
       const float* __restrict__ Wh_b, const float* __restrict__ bhn_b)
{
    __shared__ __align__(16) float hbuf[4][272];   // 4 blocks x (64 data + 4 pad)
    __shared__ __align__(16) float hist[16][64];   // output staging

    const uint32_t hbuf_a = s2u(hbuf);

    const int rank = blockIdx.x & 3;
    const int cid  = blockIdx.x >> 2;
    const int d    = cid >> 3;
    const int b    = cid & 7;

    const float* Wh  = d ? Wh_b  : Wh_f;
    const float* bhn = d ? bhn_b : bhn_f;

    const int tid  = threadIdx.x;
    const int w    = tid >> 5;
    const int lane = tid & 31;
    const int kq   = lane >> 3;                    // K-chunk of 64 (0..3)
    const int j    = lane & 7;                     // unit within warp (0..7)
    const int unit = rank * 64 + w * 8 + j;

    // ---- W slice fully in registers: 96 b64 per lane ----
    ull Wr2[32], Wz2[32], Wn2[32];
#pragma unroll
    for (int kk = 0; kk < 32; ++kk) {
        size_t r0 = (size_t)(kq * 64 + kk * 2) * G_;
        size_t r1 = r0 + G_;
        Wr2[kk] = pack2(__ldg(Wh + r0 + unit),       __ldg(Wh + r1 + unit));
        Wz2[kk] = pack2(__ldg(Wh + r0 + 256 + unit), __ldg(Wh + r1 + 256 + unit));
        Wn2[kk] = pack2(__ldg(Wh + r0 + 512 + unit), __ldg(Wh + r1 + 512 + unit));
    }

    // init: buf0 = h0 = 0, buf1..3 = canary
    for (int i = tid; i < 272; i += 256) {
        hbuf[0][i] = 0.f;
        ((unsigned*)hbuf[1])[i] = CANARY;
        ((unsigned*)hbuf[2])[i] = CANARY;
        ((unsigned*)hbuf[3])[i] = CANARY;
    }
    __syncthreads();
    asm volatile("barrier.cluster.arrive.aligned;" ::: "memory");
    asm volatile("barrier.cluster.wait.aligned;"   ::: "memory");

    // send address (lanes 0..7): peer = (rank + (lane>>1)) & 3 (incl. self),
    // half = lane&1. Warp w's 8 units live at words rank*68 + w*8 (+half*4).
    uint32_t sdata = 0;
    if (lane < 8) {
        uint32_t peer = (uint32_t)((rank + (lane >> 1)) & 3);
        uint32_t rhb;
        asm("mapa.shared::cluster.u32 %0, %1, %2;" : "=r"(rhb) : "r"(hbuf_a), "r"(peer));
        sdata = rhb + (uint32_t)(rank * 272 + w * 32 + (lane & 1) * 16);
    }

    // poll address: lane waits on producer warp j of CTA kq (8 words, 2 v4)
    const uint32_t pa = hbuf_a + (uint32_t)(kq * 272 + j * 32);
    // re-canary partition: warp w owns block (w>>1), half (w&1), word lane
    const uint32_t ca = hbuf_a + (uint32_t)((w >> 1) * 272 + (w & 1) * 128 + lane * 4);

    const float bhn_u = bhn[unit];
    const float* xgp = g_xg + ((size_t)(d * B_ + b)) * T_ * G_ + rank * 192 + w * 24;

    // 3-deep gi prefetch ring (lanes 0..23: gate = lane>>3, j = lane&7)
    float gv0 = 0.f, gv1 = 0.f, gv2 = 0.f;
    if (lane < 24) {
        gv0 = __ldg(xgp + (size_t)(d ? T_ - 1 : 0) * G_ + lane);
        gv1 = __ldg(xgp + (size_t)(d ? T_ - 2 : 1) * G_ + lane);
        gv2 = __ldg(xgp + (size_t)(d ? T_ - 3 : 2) * G_ + lane);
    }

    float hprev = 0.f;

    for (int s = 0; s < T_; ++s) {
        const int q = s & 3;

        // ---- 1. poll: this lane's producer-warp words present ----
        {
            const uint32_t a = pa + (uint32_t)q * 1088;
            for (;;) {
                uint32_t x0, x1, x2, x3, y0, y1, y2, y3;
                asm volatile("ld.volatile.shared.v4.u32 {%0,%1,%2,%3}, [%4];"
                             : "=r"(x0), "=r"(x1), "=r"(x2), "=r"(x3) : "r"(a));
                asm volatile("ld.volatile.shared.v4.u32 {%0,%1,%2,%3}, [%4];"
                             : "=r"(y0), "=r"(y1), "=r"(y2), "=r"(y3) : "r"(a + 16));
                bool bad = (x0 == CANARY) | (x1 == CANARY) | (x2 == CANARY) |
                           (x3 == CANARY) | (y0 == CANARY) | (y1 == CANARY) |
                           (y2 == CANARY) | (y3 == CANARY);
                if (!__any_sync(0xFFFFFFFFu, bad)) break;
            }
        }

        // ---- 2. re-canary buf (q+2)&3 (read-complete: all warps >= s-1) ----
        {
            const uint32_t a = ca + (uint32_t)((q + 2) & 3) * 1088;
            asm volatile("st.shared.u32 [%0], %1;" :: "r"(a), "r"(CANARY) : "memory");
        }

        // ---- 3. dots: this lane's 64-K chunk (block kq) ----
        const float* hp = &hbuf[q][kq * 68];
        ull ar0 = 0, ar1 = 0, az0 = 0, az1 = 0, an0 = 0, an1 = 0;
#pragma unroll
        for (int qq = 0; qq < 16; ++qq) {
            ulonglong2 hv2 = *(const ulonglong2*)(hp + qq * 4);
            ar0 = ffma2(Wr2[qq * 2],     hv2.x, ar0);
            ar1 = ffma2(Wr2[qq * 2 + 1], hv2.y, ar1);
            az0 = ffma2(Wz2[qq * 2],     hv2.x, az0);
            az1 = ffma2(Wz2[qq * 2 + 1], hv2.y, az1);
            an0 = ffma2(Wn2[qq * 2],     hv2.x, an0);
            an1 = ffma2(Wn2[qq * 2 + 1], hv2.y, an1);
        }
        float sr = sum2(fadd2(ar0, ar1));
        float sz = sum2(fadd2(az0, az1));
        float sn = sum2(fadd2(an0, an1));
#pragma unroll
        for (int m = 8; m <= 16; m <<= 1) {        // reduce over kq
            sr += __shfl_xor_sync(0xFFFFFFFFu, sr, m);
            sz += __shfl_xor_sync(0xFFFFFFFFu, sz, m);
            sn += __shfl_xor_sync(0xFFFFFFFFu, sn, m);
        }

        float gr = __shfl_sync(0xFFFFFFFFu, gv0, j);
        float gz = __shfl_sync(0xFFFFFFFFu, gv0, 8 + j);
        float gn = __shfl_sync(0xFFFFFFFFu, gv0, 16 + j);

        {
            float r = fast_sigmoid(gr + sr);
            float z = fast_sigmoid(gz + sz);
            float n = fast_tanh(fmaf(r, sn + bhn_u, gn));
            hprev = fmaf(z, hprev - n, n);          // h_new, all lanes
        }

        // ---- 4. send: warp's 8 units to all 4 CTAs (8 lanes x 1 v4) ----
        if (s + 1 < T_) {
            const uint32_t qoff = (uint32_t)((s + 1) & 3) * 1088;
            const int base = (lane & 1) * 4;
            float4 v;
            v.x = __shfl_sync(0xFFFFFFFFu, hprev, base + 0);
            v.y = __shfl_sync(0xFFFFFFFFu, hprev, base + 1);
            v.z = __shfl_sync(0xFFFFFFFFu, hprev, base + 2);
            v.w = __shfl_sync(0xFFFFFFFFu, hprev, base + 3);
            if (lane < 8) {
                asm volatile("st.shared::cluster.v4.b32 [%0], {%1, %2, %3, %4};"
                             :: "r"(sdata + qoff),
                                "r"(__float_as_uint(v.x)), "r"(__float_as_uint(v.y)),
                                "r"(__float_as_uint(v.z)), "r"(__float_as_uint(v.w))
                             : "memory");
            }
            // advance gi ring (prefetch s+3)
            gv0 = gv1; gv1 = gv2;
            if (lane < 24 && s + 3 < T_) {
                const int tn = d ? (T_ - 4 - s) : (s + 3);
                gv2 = __ldg(xgp + (size_t)tn * G_ + lane);
            }
        }

        // ---- 5. stage output ----
        if (lane < 8) hist[s & 15][w * 8 + lane] = hprev;

        // ---- 6. skew-safe flush: rows [s-14, s-7] (all provably written) ----
        if ((s & 7) == 7) {
            const int rr = s - 14 + w;
            if (rr >= 0) {
                const int tw = d ? (T_ - 1 - rr) : rr;
                *(float2*)&g_outc[((size_t)b * T_ + tw) * 512 + d * 256 +
                                  rank * 64 + lane * 2] =
                    *(const float2*)&hist[rr & 15][lane * 2];
            }
        }
    }

    // tail: rows 4089..4095 (warps 1..7), after all warps finish
    __syncthreads();
    if (w >= 1) {
        const int rr = 4088 + w;
        const int tw = d ? (T_ - 1 - rr) : rr;
        *(float2*)&g_outc[((size_t)b * T_ + tw) * 512 + d * 256 +
                          rank * 64 + lane * 2] =
            *(const float2*)&hist[rr & 15][lane * 2];
    }

    // no CTA may exit while peers can still write its smem
    asm volatile("barrier.cluster.arrive.aligned;" ::: "memory");
    asm volatile("barrier.cluster.wait.aligned;"   ::: "memory");
}

// ---------------------------------------------------------------------------
// Kernel C: heads. out_combined [32768,512] @ (Wm|Wv) [512,256] + bias. FFMA2.
// ---------------------------------------------------------------------------
__global__ void __launch_bounds__(256) k_heads(
    const float* __restrict__ Wm, const float* __restrict__ bm,
    const float* __restrict__ Wv, const float* __restrict__ bv,
    float* __restrict__ out)
{
    const int n0 = blockIdx.x * 64;
    const int m0 = blockIdx.y * 128;
    const bool isV = (n0 >= 256);
    const float* W  = isV ? Wv : Wm;
    const float* bb = isV ? bv : bm;
    const int nw = n0 & 255;

    __shared__ __align__(16) float As[16][136];
    __shared__ __align__(16) ull   Bs2[16][64];

    const int tid = threadIdx.x;
    const int ti = tid >> 4, tj = tid & 15;

    ull acc2[4][4];
#pragma unroll
    for (int i = 0; i < 4; ++i)
#pragma unroll
        for (int j = 0; j < 4; ++j) acc2[i][j] = 0ull;

    for (int k0 = 0; k0 < 512; k0 += 16) {
#pragma unroll
        for (int p = 0; p < 8; ++p) {
            int idx = tid + p * 256;
            int r = idx >> 4, c = idx & 15;
            As[c][r] = g_outc[(size_t)(m0 + r) * 512 + k0 + c];
        }
#pragma unroll
        for (int p = 0; p < 4; ++p) {
            int idx = tid + p * 256;
            int r = idx >> 6, c = idx & 63;
            float bv2 = W[(size_t)(k0 + r) * 256 + nw + c];
            Bs2[r][c] = pack2(bv2, bv2);
        }
        __syncthreads();
#pragma unroll
        for (int kk = 0; kk < 16; ++kk) {
            ull ap[4];
            const ull* arow = (const ull*)&As[kk][ti * 8];
            ap[0] = arow[0]; ap[1] = arow[1]; ap[2] = arow[2]; ap[3] = arow[3];
            ull bd[4];
            const ull* brow = &Bs2[kk][tj * 4];
            bd[0] = brow[0]; bd[1] = brow[1]; bd[2] = brow[2]; bd[3] = brow[3];
#pragma unroll
            for (int i = 0; i < 4; ++i)
#pragma unroll
                for (int jj = 0; jj < 4; ++jj)
                    acc2[i][jj] = ffma2(ap[i], bd[jj], acc2[i][jj]);
        }
        __syncthreads();
    }

    const size_t hofs = (size_t)M_ * H_;
    float4 bb4 = *(const float4*)&bb[nw + tj * 4];
#pragma unroll
    for (int i = 0; i < 4; ++i) {
        float4 o0, o1;
        unpack2(acc2[i][0], o0.x, o1.x);
        unpack2(acc2[i][1], o0.y, o1.y);
        unpack2(acc2[i][2], o0.z, o1.z);
        unpack2(acc2[i][3], o0.w, o1.w);
        o0.x += bb4.x; o0.y += bb4.y; o0.z += bb4.z; o0.w += bb4.w;
        o1.x += bb4.x; o1.y += bb4.y; o1.z += bb4.z; o1.w += bb4.w;
        int r0 = m0 + ti * 8 + i * 2, r1 = r0 + 1;
        if (isV) {
            o0.x = expf(o0.x); o0.y = expf(o0.y); o0.z = expf(o0.z); o0.w = expf(o0.w);
            o1.x = expf(o1.x); o1.y = expf(o1.y); o1.z = expf(o1.z); o1.w = expf(o1.w);
            *(float4*)&out[(size_t)r0 * 256 + nw + tj * 4] = o0;
            *(float4*)&out[(size_t)r1 * 256 + nw + tj * 4] = o1;
        } else {
            *(float4*)&out[hofs + (size_t)r0 * 256 + nw + tj * 4] = o0;
            *(float4*)&out[hofs + (size_t)r1 * 256 + nw + tj * 4] = o1;
        }
    }
}

// ---------------------------------------------------------------------------
extern "C" void kernel_launch(void* const* d_in, const int* in_sizes, int n_in,
                              void* d_out, int out_size)
{
    const float* inputs = (const float*)d_in[0];
    const float* Wi_f   = (const float*)d_in[1];
    const float* bi_f   = (const float*)d_in[2];
    const float* Wh_f   = (const float*)d_in[3];
    const float* bhn_f  = (const float*)d_in[4];
    const float* Wi_b   = (const float*)d_in[5];
    const float* bi_b   = (const float*)d_in[6];
    const float* Wh_b   = (const float*)d_in[7];
    const float* bhn_b  = (const float*)d_in[8];
    const float* Wm     = (const float*)d_in[9];
    const float* bm     = (const float*)d_in[10];
    const float* Wv     = (const float*)d_in[11];
    const float* bv     = (const float*)d_in[12];
    float* out = (float*)d_out;

    (void)in_sizes; (void)n_in; (void)out_size;

    k_xgemm<<<dim3(12, 256, 2), 256>>>(inputs, Wi_f, bi_f, Wi_b, bi_b);
    k_scan<<<64, 256>>>(Wh_f, bhn_f, Wh_b, bhn_b);
    k_heads<<<dim3(8, 256), 256>>>(Wm, bm, Wv, bv, out);
}